// round 7
// baseline (speedup 1.0000x reference)
#include <cuda_runtime.h>
#include <cuda_bf16.h>
#include <cstdint>

// Problem constants
#define B_      32
#define C_      256
#define HW_     1024
#define NTOK    32768
#define KCODES  1024
#define BETA    0.25f

// Output layout (concatenated float32): u, z_train, vq_loss, indices
#define SZ_U    8388608
#define OFF_U   0
#define OFF_ZT  8388608
#define OFF_LOSS 16777216
#define OFF_IDX  16777217

// GEMM tiling
#define TOKT 256
#define CODT 64
#define NTILE (KCODES / CODT)   // 16
#define SA   264        // A smem stride: %32==8 -> conflict-free frags
#define SB   36         // B smem stride: %32==4 -> conflict-free frags
#define MARGIN 1e-4f    // split-tf32 + fp32-accum pair bound (5x headroom)

#define GEMM_SMEM ((64 * SA + 2 * 64 * SB) * 4)   // 86016 B

// Device scratch
__device__ float g_codebookT[C_ * KCODES];     // [c][code]
__device__ float g_cnorm[KCODES];
__device__ float g_cbhi[KCODES * C_];          // [code][c] tf32-hi
__device__ float g_cblo[KCODES * C_];          // [code][c] tf32-lo
__device__ float g_uhi[NTOK * C_];             // [b][c][hw] tf32-hi, 32 MB
__device__ float g_ulo[NTOK * C_];             // [b][c][hw] tf32-lo, 32 MB
__device__ int   g_idx[NTOK];
__device__ float g_partial[B_ * C_];
__device__ float g_t1v[NTILE * NTOK];
__device__ int   g_t1i[NTILE * NTOK];
__device__ float g_t2v[NTILE * NTOK];
__device__ int   g_nambig;
__device__ int   g_ambig[NTOK];
__device__ float g_lim[NTOK];

// ---------------------------------------------------------------------------
__device__ __forceinline__ float to_tf32f(float f) {
    uint32_t r;
    asm("cvt.rna.tf32.f32 %0, %1;" : "=r"(r) : "f"(f));
    return __uint_as_float(r);
}

__device__ __forceinline__ void mma_tf32(float* c, const uint32_t* a,
                                         const uint32_t* b) {
    asm volatile(
        "mma.sync.aligned.m16n8k8.row.col.f32.tf32.tf32.f32 "
        "{%0,%1,%2,%3}, {%4,%5,%6,%7}, {%8,%9}, {%0,%1,%2,%3};"
        : "+f"(c[0]), "+f"(c[1]), "+f"(c[2]), "+f"(c[3])
        : "r"(a[0]), "r"(a[1]), "r"(a[2]), "r"(a[3]), "r"(b[0]), "r"(b[1]));
}

__device__ __forceinline__ void upd_min2(float v, int i, float& m1, int& i1,
                                         float& m2) {
    if (v < m1) { m2 = m1; m1 = v; i1 = i; }
    else if (v < m2) { m2 = v; }
}

__device__ __forceinline__ void merge_min2(float& v1, int& i1, float& v2,
                                           float ov1, int oi1, float ov2) {
    if (ov1 < v1 || (ov1 == v1 && oi1 < i1)) {
        v2 = fminf(v1, ov2);
        v1 = ov1; i1 = oi1;
    } else {
        v2 = fminf(v2, ov1);
    }
}

// ---------------------------------------------------------------------------
// K0a: codebook prep: transpose + |c|^2 + hi/lo split + zero ambig counter
// ---------------------------------------------------------------------------
__global__ void __launch_bounds__(256) prep_kernel(const float* __restrict__ cb) {
    __shared__ float s[256];
    int k = blockIdx.x;
    int c = threadIdx.x;
    if (k == 0 && c == 0) g_nambig = 0;
    float v = cb[k * C_ + c];
    g_codebookT[c * KCODES + k] = v;
    float h = to_tf32f(v);
    g_cbhi[k * C_ + c] = h;
    g_cblo[k * C_ + c] = to_tf32f(v - h);
    s[c] = v * v;
    __syncthreads();
    #pragma unroll
    for (int stride = 128; stride > 0; stride >>= 1) {
        if (c < stride) s[c] += s[c + stride];
        __syncthreads();
    }
    if (c == 0) g_cnorm[k] = s[0];
}

// K0b: split u into tf32 hi/lo. 1024 blocks x 256 threads x 8 float4
// = 1024 * 2048 float4 = 8,388,608 floats exactly.
__global__ void __launch_bounds__(256) prep_u_kernel(const float* __restrict__ u) {
    const float4* u4 = (const float4*)u;
    float4* h4 = (float4*)g_uhi;
    float4* l4 = (float4*)g_ulo;
    const size_t base4 = (size_t)blockIdx.x * 2048 + (size_t)threadIdx.x * 8;
    #pragma unroll
    for (int p = 0; p < 8; ++p) {
        float4 v = u4[base4 + p];
        float4 h, l;
        h.x = to_tf32f(v.x); l.x = to_tf32f(v.x - h.x);
        h.y = to_tf32f(v.y); l.y = to_tf32f(v.y - h.y);
        h.z = to_tf32f(v.z); l.z = to_tf32f(v.z - h.z);
        h.w = to_tf32f(v.w); l.w = to_tf32f(v.w - h.w);
        h4[base4 + p] = h;
        l4[base4 + p] = l;
    }
}

// ---------------------------------------------------------------------------
// K1: split-tf32 tensor GEMM with fused per-tile argmin.
// dot = hi.hi + lo.hi + hi.lo ; staging is pure copy from precomputed hi/lo.
// grid (16 code-tiles, 128 token-tiles), 256 threads
// ---------------------------------------------------------------------------
__global__ void __launch_bounds__(256, 2) gemm_kernel() {
    extern __shared__ float sm[];
    float* Ah = sm;                    // [32][SA]
    float* Al = sm + 32 * SA;
    float* Bh = sm + 64 * SA;          // [64][SB]
    float* Bl = Bh + 64 * SB;

    const int tid = threadIdx.x;
    const int w = tid >> 5, lane = tid & 31;
    const int g = lane >> 2, q = lane & 3;
    const int code0 = blockIdx.x * CODT;
    const int tok0 = blockIdx.y * TOKT;
    const int b = tok0 >> 10, hw0 = tok0 & 1023;
    const size_t ubase = (size_t)b * (C_ * HW_) + hw0;

    float acc[2][8][4];
    #pragma unroll
    for (int m = 0; m < 2; ++m)
        #pragma unroll
        for (int j = 0; j < 8; ++j)
            #pragma unroll
            for (int e = 0; e < 4; ++e) acc[m][j][e] = 0.f;

    const uint32_t* Ahu = (const uint32_t*)Ah;
    const uint32_t* Alu = (const uint32_t*)Al;
    const uint32_t* Bhu = (const uint32_t*)Bh;
    const uint32_t* Blu = (const uint32_t*)Bl;

    for (int kc = 0; kc < 8; ++kc) {
        const int k0 = kc * 32;
        // stage A: pure copies of precomputed hi/lo
        #pragma unroll
        for (int p = 0; p < 8; ++p) {
            int f = tid + p * 256;
            int kr = f >> 6, t4 = (f & 63) << 2;
            const size_t gofs = ubase + (size_t)(k0 + kr) * HW_ + t4;
            *(float4*)&Ah[kr * SA + t4] = *(const float4*)&g_uhi[gofs];
            *(float4*)&Al[kr * SA + t4] = *(const float4*)&g_ulo[gofs];
        }
        // stage B
        #pragma unroll
        for (int p = 0; p < 2; ++p) {
            int f = tid + p * 256;
            int cr = f >> 3, k4 = (f & 7) << 2;
            const size_t gofs = (size_t)(code0 + cr) * C_ + k0 + k4;
            *(float4*)&Bh[cr * SB + k4] = *(const float4*)&g_cbhi[gofs];
            *(float4*)&Bl[cr * SB + k4] = *(const float4*)&g_cblo[gofs];
        }
        __syncthreads();

        #pragma unroll
        for (int ks = 0; ks < 4; ++ks) {
            const int kb = ks * 8;
            uint32_t bf[8][2];
            // pass 1+2: B hi with A hi and A lo
            #pragma unroll
            for (int j = 0; j < 8; ++j) {
                int row = (j * 8 + g) * SB + kb + q;
                bf[j][0] = Bhu[row];
                bf[j][1] = Bhu[row + 4];
            }
            #pragma unroll
            for (int m = 0; m < 2; ++m) {
                const int arow = w * 32 + m * 16 + g;
                uint32_t af[4];
                af[0] = Ahu[(kb + q) * SA + arow];
                af[1] = Ahu[(kb + q) * SA + arow + 8];
                af[2] = Ahu[(kb + q + 4) * SA + arow];
                af[3] = Ahu[(kb + q + 4) * SA + arow + 8];
                #pragma unroll
                for (int j = 0; j < 8; ++j) mma_tf32(acc[m][j], af, bf[j]);
                af[0] = Alu[(kb + q) * SA + arow];
                af[1] = Alu[(kb + q) * SA + arow + 8];
                af[2] = Alu[(kb + q + 4) * SA + arow];
                af[3] = Alu[(kb + q + 4) * SA + arow + 8];
                #pragma unroll
                for (int j = 0; j < 8; ++j) mma_tf32(acc[m][j], af, bf[j]);
            }
            // pass 3: B lo with A hi
            #pragma unroll
            for (int j = 0; j < 8; ++j) {
                int row = (j * 8 + g) * SB + kb + q;
                bf[j][0] = Blu[row];
                bf[j][1] = Blu[row + 4];
            }
            #pragma unroll
            for (int m = 0; m < 2; ++m) {
                const int arow = w * 32 + m * 16 + g;
                uint32_t af[4];
                af[0] = Ahu[(kb + q) * SA + arow];
                af[1] = Ahu[(kb + q) * SA + arow + 8];
                af[2] = Ahu[(kb + q + 4) * SA + arow];
                af[3] = Ahu[(kb + q + 4) * SA + arow + 8];
                #pragma unroll
                for (int j = 0; j < 8; ++j) mma_tf32(acc[m][j], af, bf[j]);
            }
        }
        __syncthreads();
    }

    // fused per-tile argmin epilogue
    #pragma unroll
    for (int m = 0; m < 2; ++m) {
        float m1a = 3.4e38f, m2a = 3.4e38f; int i1a = 0;
        float m1b = 3.4e38f, m2b = 3.4e38f; int i1b = 0;
        #pragma unroll
        for (int j = 0; j < 8; ++j) {
            const int col = code0 + j * 8 + q * 2;
            const float cn0 = __ldg(&g_cnorm[col]);
            const float cn1 = __ldg(&g_cnorm[col + 1]);
            upd_min2(fmaf(-2.f, acc[m][j][0], cn0), col,     m1a, i1a, m2a);
            upd_min2(fmaf(-2.f, acc[m][j][1], cn1), col + 1, m1a, i1a, m2a);
            upd_min2(fmaf(-2.f, acc[m][j][2], cn0), col,     m1b, i1b, m2b);
            upd_min2(fmaf(-2.f, acc[m][j][3], cn1), col + 1, m1b, i1b, m2b);
        }
        #pragma unroll
        for (int off = 1; off <= 2; off <<= 1) {
            float ov1 = __shfl_xor_sync(0xffffffffu, m1a, off);
            int   oi1 = __shfl_xor_sync(0xffffffffu, i1a, off);
            float ov2 = __shfl_xor_sync(0xffffffffu, m2a, off);
            merge_min2(m1a, i1a, m2a, ov1, oi1, ov2);
            ov1 = __shfl_xor_sync(0xffffffffu, m1b, off);
            oi1 = __shfl_xor_sync(0xffffffffu, i1b, off);
            ov2 = __shfl_xor_sync(0xffffffffu, m2b, off);
            merge_min2(m1b, i1b, m2b, ov1, oi1, ov2);
        }
        if (q == 0) {
            const int t_lo = tok0 + w * 32 + m * 16 + g;
            const size_t base = (size_t)blockIdx.x * NTOK;
            g_t1v[base + t_lo] = m1a;
            g_t1i[base + t_lo] = i1a;
            g_t2v[base + t_lo] = m2a;
            g_t1v[base + t_lo + 8] = m1b;
            g_t1i[base + t_lo + 8] = i1b;
            g_t2v[base + t_lo + 8] = m2b;
        }
    }
}

// ---------------------------------------------------------------------------
// K2: merge tile summaries; margin check; build ambiguous worklist.
// ---------------------------------------------------------------------------
__global__ void __launch_bounds__(256) reduce_kernel(float* __restrict__ out_idx) {
    const int tok = blockIdx.x * 256 + threadIdx.x;
    float m1 = 3.4e38f, m2 = 3.4e38f;
    int i1 = 0;
    #pragma unroll
    for (int t = 0; t < NTILE; ++t) {
        const size_t p = (size_t)t * NTOK + tok;
        merge_min2(m1, i1, m2, g_t1v[p], g_t1i[p], g_t2v[p]);
    }
    g_idx[tok] = i1;
    out_idx[tok] = (float)i1;
    if (m2 - m1 <= MARGIN) {
        int slot = atomicAdd(&g_nambig, 1);
        g_ambig[slot] = tok;
        g_lim[slot] = m1 + MARGIN;
    }
}

// ---------------------------------------------------------------------------
// K3: exact fp32 rescue, tile-filtered, coalesced codebookT reads.
// ---------------------------------------------------------------------------
__global__ void __launch_bounds__(256) rescue_kernel(const float* __restrict__ u,
                                                     float* __restrict__ out_idx) {
    __shared__ float us[8][C_];
    const int wid = threadIdx.x >> 5, lane = threadIdx.x & 31;
    const int gw = blockIdx.x * 8 + wid;
    const int nwarps = gridDim.x * 8;
    const int n = g_nambig;

    for (int i = gw; i < n; i += nwarps) {
        const int tok = g_ambig[i];
        const float lim = g_lim[i];
        const int b = tok >> 10, hw = tok & 1023;
        #pragma unroll
        for (int r = 0; r < 8; ++r) {
            int c = lane + r * 32;
            us[wid][c] = u[((size_t)(b * C_ + c) << 10) + hw];
        }
        __syncwarp();
        float best = 3.4e38f;
        int bi = KCODES;
        for (int t = 0; t < NTILE; ++t) {
            if (g_t1v[(size_t)t * NTOK + tok] > lim) continue;
            const int cb0 = t * CODT;
            const int c0 = cb0 + lane, c1 = cb0 + lane + 32;
            float d0 = 0.f, d1 = 0.f;
            #pragma unroll 8
            for (int k = 0; k < C_; ++k) {
                const float uv = us[wid][k];
                const float* row = g_codebookT + (size_t)k * KCODES + cb0;
                d0 = fmaf(uv, row[lane], d0);
                d1 = fmaf(uv, row[lane + 32], d1);
            }
            const float s0 = fmaf(-2.f, d0, g_cnorm[c0]);
            const float s1 = fmaf(-2.f, d1, g_cnorm[c1]);
            if (s0 < best || (s0 == best && c0 < bi)) { best = s0; bi = c0; }
            if (s1 < best || (s1 == best && c1 < bi)) { best = s1; bi = c1; }
        }
        #pragma unroll
        for (int off = 16; off > 0; off >>= 1) {
            float ov = __shfl_xor_sync(0xffffffffu, best, off);
            int oi = __shfl_xor_sync(0xffffffffu, bi, off);
            if (ov < best || (ov == best && oi < bi)) { best = ov; bi = oi; }
        }
        if (lane == 0) {
            g_idx[tok] = bi;
            out_idx[tok] = (float)bi;
        }
        __syncwarp();
    }
}

// ---------------------------------------------------------------------------
// K4: outputs. copy u, gather z_q, accumulate (z_q - u)^2 per (b,c)
// ---------------------------------------------------------------------------
__global__ void __launch_bounds__(256) epilogue_kernel(const float* __restrict__ u,
                                                       float* __restrict__ out) {
    __shared__ float col[KCODES];
    __shared__ float sred[256];
    const int c = blockIdx.x;
    const int b = blockIdx.y;
    const int tid = threadIdx.x;

    ((float4*)col)[tid] = ((const float4*)(g_codebookT + c * KCODES))[tid];
    __syncthreads();

    const long base = ((long)(b * C_ + c)) << 10;
    const float* ub = u + base;
    float* ou = out + OFF_U + base;
    float* oz = out + OFF_ZT + base;
    const int* ib = g_idx + (b << 10);

    float acc = 0.f;
    #pragma unroll
    for (int j = 0; j < 4; ++j) {
        int hw = tid + (j << 8);
        int i = ib[hw];
        float z = col[i];
        float uu = ub[hw];
        ou[hw] = uu;
        oz[hw] = z;
        float d = z - uu;
        acc = fmaf(d, d, acc);
    }
    sred[tid] = acc;
    __syncthreads();
    #pragma unroll
    for (int stride = 128; stride > 0; stride >>= 1) {
        if (tid < stride) sred[tid] += sred[tid + stride];
        __syncthreads();
    }
    if (tid == 0) g_partial[b * C_ + c] = sred[0];
}

// ---------------------------------------------------------------------------
// K5: final loss. vq = (1 + BETA) * mean((z_q - u)^2)
// ---------------------------------------------------------------------------
__global__ void __launch_bounds__(256) loss_kernel(float* __restrict__ out) {
    __shared__ float s[256];
    const int tid = threadIdx.x;
    float a = 0.f;
    for (int i = tid; i < B_ * C_; i += 256) a += g_partial[i];
    s[tid] = a;
    __syncthreads();
    #pragma unroll
    for (int stride = 128; stride > 0; stride >>= 1) {
        if (tid < stride) s[tid] += s[tid + stride];
        __syncthreads();
    }
    if (tid == 0)
        out[OFF_LOSS] = s[0] * (1.0f + BETA) / (float)SZ_U;
}

// ---------------------------------------------------------------------------
extern "C" void kernel_launch(void* const* d_in, const int* in_sizes, int n_in,
                              void* d_out, int out_size) {
    const float* u  = (const float*)d_in[0];
    const float* cb = (const float*)d_in[1];
    float* out = (float*)d_out;

    static bool attr_done = false;
    if (!attr_done) {
        cudaFuncSetAttribute(gemm_kernel,
                             cudaFuncAttributeMaxDynamicSharedMemorySize,
                             GEMM_SMEM);
        attr_done = true;
    }

    prep_kernel<<<KCODES, 256>>>(cb);
    prep_u_kernel<<<1024, 256>>>(u);
    gemm_kernel<<<dim3(NTILE, NTOK / TOKT), 256, GEMM_SMEM>>>();
    reduce_kernel<<<NTOK / 256, 256>>>(out + OFF_IDX);
    rescue_kernel<<<256, 256>>>(u, out + OFF_IDX);
    epilogue_kernel<<<dim3(C_, B_), 256>>>(u, out);
    loss_kernel<<<1, 256>>>(out);
}

// round 8
// speedup vs baseline: 1.1951x; 1.1951x over previous
#include <cuda_runtime.h>
#include <cuda_bf16.h>
#include <cstdint>

// Problem constants
#define B_      32
#define C_      256
#define HW_     1024
#define NTOK    32768
#define KCODES  1024
#define BETA    0.25f

// Output layout (concatenated float32): u, z_train, vq_loss, indices
#define SZ_U    8388608
#define OFF_U   0
#define OFF_ZT  8388608
#define OFF_LOSS 16777216
#define OFF_IDX  16777217

// GEMM tiling
#define TOKT 256
#define CODT 64
#define NTILE (KCODES / CODT)   // 16
#define SA   264        // A smem stride: %32==8 -> conflict-free frags
#define SB   36         // B smem stride: %32==4 -> conflict-free frags
#define MARGIN 1e-4f    // split-tf32 + fp32-accum pair bound (5x headroom)

#define GEMM_SMEM ((64 * SA + 2 * 64 * SB) * 4)   // 86016 B

// Device scratch
__device__ float g_codebookT[C_ * KCODES];     // [c][code]
__device__ float g_cnorm[KCODES];
__device__ int   g_idx[NTOK];
__device__ float g_partial[B_ * C_];
__device__ float g_t1v[NTILE * NTOK];
__device__ int   g_t1i[NTILE * NTOK];
__device__ float g_t2v[NTILE * NTOK];
__device__ int   g_nambig;
__device__ int   g_ambig[NTOK];
__device__ float g_lim[NTOK];

// ---------------------------------------------------------------------------
__device__ __forceinline__ float to_tf32f(float f) {
    uint32_t r;
    asm("cvt.rna.tf32.f32 %0, %1;" : "=r"(r) : "f"(f));
    return __uint_as_float(r);
}

__device__ __forceinline__ void mma_tf32(float* c, const uint32_t* a,
                                         const uint32_t* b) {
    asm volatile(
        "mma.sync.aligned.m16n8k8.row.col.f32.tf32.tf32.f32 "
        "{%0,%1,%2,%3}, {%4,%5,%6,%7}, {%8,%9}, {%0,%1,%2,%3};"
        : "+f"(c[0]), "+f"(c[1]), "+f"(c[2]), "+f"(c[3])
        : "r"(a[0]), "r"(a[1]), "r"(a[2]), "r"(a[3]), "r"(b[0]), "r"(b[1]));
}

__device__ __forceinline__ void upd_min2(float v, int i, float& m1, int& i1,
                                         float& m2) {
    if (v < m1) { m2 = m1; m1 = v; i1 = i; }
    else if (v < m2) { m2 = v; }
}

__device__ __forceinline__ void merge_min2(float& v1, int& i1, float& v2,
                                           float ov1, int oi1, float ov2) {
    if (ov1 < v1 || (ov1 == v1 && oi1 < i1)) {
        v2 = fminf(v1, ov2);
        v1 = ov1; i1 = oi1;
    } else {
        v2 = fminf(v2, ov1);
    }
}

// ---------------------------------------------------------------------------
// K0: codebook transpose + |c|^2 + zero ambig counter
// ---------------------------------------------------------------------------
__global__ void __launch_bounds__(256) prep_kernel(const float* __restrict__ cb) {
    __shared__ float s[256];
    int k = blockIdx.x;
    int c = threadIdx.x;
    if (k == 0 && c == 0) g_nambig = 0;
    float v = cb[k * C_ + c];
    g_codebookT[c * KCODES + k] = v;
    s[c] = v * v;
    __syncthreads();
    #pragma unroll
    for (int stride = 128; stride > 0; stride >>= 1) {
        if (c < stride) s[c] += s[c + stride];
        __syncthreads();
    }
    if (c == 0) g_cnorm[k] = s[0];
}

// ---------------------------------------------------------------------------
// K1: split-tf32 tensor GEMM with fused per-tile argmin (R5 configuration:
// hi/lo split inline during staging — recompute beats re-load on L1-bound).
// dot = hi.hi + lo.hi + hi.lo  (error ~2e-5)
// grid (16 code-tiles, 128 token-tiles), 256 threads
// ---------------------------------------------------------------------------
__global__ void __launch_bounds__(256, 2) gemm_kernel(const float* __restrict__ u,
                                                      const float* __restrict__ cb) {
    extern __shared__ float sm[];
    float* Ah = sm;                    // [32][SA]
    float* Al = sm + 32 * SA;
    float* Bh = sm + 64 * SA;          // [64][SB]
    float* Bl = Bh + 64 * SB;

    const int tid = threadIdx.x;
    const int w = tid >> 5, lane = tid & 31;
    const int g = lane >> 2, q = lane & 3;
    const int code0 = blockIdx.x * CODT;
    const int tok0 = blockIdx.y * TOKT;
    const int b = tok0 >> 10, hw0 = tok0 & 1023;
    const float* ub = u + (size_t)b * (C_ * HW_) + hw0;

    float acc[2][8][4];
    #pragma unroll
    for (int m = 0; m < 2; ++m)
        #pragma unroll
        for (int j = 0; j < 8; ++j)
            #pragma unroll
            for (int e = 0; e < 4; ++e) acc[m][j][e] = 0.f;

    const uint32_t* Ahu = (const uint32_t*)Ah;
    const uint32_t* Alu = (const uint32_t*)Al;
    const uint32_t* Bhu = (const uint32_t*)Bh;
    const uint32_t* Blu = (const uint32_t*)Bl;

    for (int kc = 0; kc < 8; ++kc) {
        const int k0 = kc * 32;
        // stage A: 32 k-rows x 256 tokens -> hi/lo
        #pragma unroll
        for (int p = 0; p < 8; ++p) {
            int f = tid + p * 256;
            int kr = f >> 6, t4 = (f & 63) << 2;
            float4 v = *(const float4*)&ub[(size_t)(k0 + kr) * HW_ + t4];
            float4 h, l;
            h.x = to_tf32f(v.x); l.x = to_tf32f(v.x - h.x);
            h.y = to_tf32f(v.y); l.y = to_tf32f(v.y - h.y);
            h.z = to_tf32f(v.z); l.z = to_tf32f(v.z - h.z);
            h.w = to_tf32f(v.w); l.w = to_tf32f(v.w - h.w);
            *(float4*)&Ah[kr * SA + t4] = h;
            *(float4*)&Al[kr * SA + t4] = l;
        }
        // stage B: 64 codes x 32 k -> hi/lo
        #pragma unroll
        for (int p = 0; p < 2; ++p) {
            int f = tid + p * 256;
            int cr = f >> 3, k4 = (f & 7) << 2;
            float4 v = *(const float4*)&cb[(size_t)(code0 + cr) * C_ + k0 + k4];
            float4 h, l;
            h.x = to_tf32f(v.x); l.x = to_tf32f(v.x - h.x);
            h.y = to_tf32f(v.y); l.y = to_tf32f(v.y - h.y);
            h.z = to_tf32f(v.z); l.z = to_tf32f(v.z - h.z);
            h.w = to_tf32f(v.w); l.w = to_tf32f(v.w - h.w);
            *(float4*)&Bh[cr * SB + k4] = h;
            *(float4*)&Bl[cr * SB + k4] = l;
        }
        __syncthreads();

        #pragma unroll
        for (int ks = 0; ks < 4; ++ks) {
            const int kb = ks * 8;
            uint32_t bf[8][2];
            // pass 1+2: B hi with A hi and A lo
            #pragma unroll
            for (int j = 0; j < 8; ++j) {
                int row = (j * 8 + g) * SB + kb + q;
                bf[j][0] = Bhu[row];
                bf[j][1] = Bhu[row + 4];
            }
            #pragma unroll
            for (int m = 0; m < 2; ++m) {
                const int arow = w * 32 + m * 16 + g;
                uint32_t af[4];
                af[0] = Ahu[(kb + q) * SA + arow];
                af[1] = Ahu[(kb + q) * SA + arow + 8];
                af[2] = Ahu[(kb + q + 4) * SA + arow];
                af[3] = Ahu[(kb + q + 4) * SA + arow + 8];
                #pragma unroll
                for (int j = 0; j < 8; ++j) mma_tf32(acc[m][j], af, bf[j]);
                af[0] = Alu[(kb + q) * SA + arow];
                af[1] = Alu[(kb + q) * SA + arow + 8];
                af[2] = Alu[(kb + q + 4) * SA + arow];
                af[3] = Alu[(kb + q + 4) * SA + arow + 8];
                #pragma unroll
                for (int j = 0; j < 8; ++j) mma_tf32(acc[m][j], af, bf[j]);
            }
            // pass 3: B lo with A hi
            #pragma unroll
            for (int j = 0; j < 8; ++j) {
                int row = (j * 8 + g) * SB + kb + q;
                bf[j][0] = Blu[row];
                bf[j][1] = Blu[row + 4];
            }
            #pragma unroll
            for (int m = 0; m < 2; ++m) {
                const int arow = w * 32 + m * 16 + g;
                uint32_t af[4];
                af[0] = Ahu[(kb + q) * SA + arow];
                af[1] = Ahu[(kb + q) * SA + arow + 8];
                af[2] = Ahu[(kb + q + 4) * SA + arow];
                af[3] = Ahu[(kb + q + 4) * SA + arow + 8];
                #pragma unroll
                for (int j = 0; j < 8; ++j) mma_tf32(acc[m][j], af, bf[j]);
            }
        }
        __syncthreads();
    }

    // fused per-tile argmin epilogue
    #pragma unroll
    for (int m = 0; m < 2; ++m) {
        float m1a = 3.4e38f, m2a = 3.4e38f; int i1a = 0;
        float m1b = 3.4e38f, m2b = 3.4e38f; int i1b = 0;
        #pragma unroll
        for (int j = 0; j < 8; ++j) {
            const int col = code0 + j * 8 + q * 2;
            const float cn0 = __ldg(&g_cnorm[col]);
            const float cn1 = __ldg(&g_cnorm[col + 1]);
            upd_min2(fmaf(-2.f, acc[m][j][0], cn0), col,     m1a, i1a, m2a);
            upd_min2(fmaf(-2.f, acc[m][j][1], cn1), col + 1, m1a, i1a, m2a);
            upd_min2(fmaf(-2.f, acc[m][j][2], cn0), col,     m1b, i1b, m2b);
            upd_min2(fmaf(-2.f, acc[m][j][3], cn1), col + 1, m1b, i1b, m2b);
        }
        #pragma unroll
        for (int off = 1; off <= 2; off <<= 1) {
            float ov1 = __shfl_xor_sync(0xffffffffu, m1a, off);
            int   oi1 = __shfl_xor_sync(0xffffffffu, i1a, off);
            float ov2 = __shfl_xor_sync(0xffffffffu, m2a, off);
            merge_min2(m1a, i1a, m2a, ov1, oi1, ov2);
            ov1 = __shfl_xor_sync(0xffffffffu, m1b, off);
            oi1 = __shfl_xor_sync(0xffffffffu, i1b, off);
            ov2 = __shfl_xor_sync(0xffffffffu, m2b, off);
            merge_min2(m1b, i1b, m2b, ov1, oi1, ov2);
        }
        if (q == 0) {
            const int t_lo = tok0 + w * 32 + m * 16 + g;
            const size_t base = (size_t)blockIdx.x * NTOK;
            g_t1v[base + t_lo] = m1a;
            g_t1i[base + t_lo] = i1a;
            g_t2v[base + t_lo] = m2a;
            g_t1v[base + t_lo + 8] = m1b;
            g_t1i[base + t_lo + 8] = i1b;
            g_t2v[base + t_lo + 8] = m2b;
        }
    }
}

// ---------------------------------------------------------------------------
// K2: merge tile summaries; margin check; build ambiguous worklist.
// ---------------------------------------------------------------------------
__global__ void __launch_bounds__(256) reduce_kernel(float* __restrict__ out_idx) {
    const int tok = blockIdx.x * 256 + threadIdx.x;
    float m1 = 3.4e38f, m2 = 3.4e38f;
    int i1 = 0;
    #pragma unroll
    for (int t = 0; t < NTILE; ++t) {
        const size_t p = (size_t)t * NTOK + tok;
        merge_min2(m1, i1, m2, g_t1v[p], g_t1i[p], g_t2v[p]);
    }
    g_idx[tok] = i1;
    out_idx[tok] = (float)i1;
    if (m2 - m1 <= MARGIN) {
        int slot = atomicAdd(&g_nambig, 1);
        g_ambig[slot] = tok;
        g_lim[slot] = m1 + MARGIN;
    }
}

// ---------------------------------------------------------------------------
// K3: exact fp32 rescue, tile-filtered, coalesced codebookT reads.
// ---------------------------------------------------------------------------
__global__ void __launch_bounds__(256) rescue_kernel(const float* __restrict__ u,
                                                     float* __restrict__ out_idx) {
    __shared__ float us[8][C_];
    const int wid = threadIdx.x >> 5, lane = threadIdx.x & 31;
    const int gw = blockIdx.x * 8 + wid;
    const int nwarps = gridDim.x * 8;
    const int n = g_nambig;

    for (int i = gw; i < n; i += nwarps) {
        const int tok = g_ambig[i];
        const float lim = g_lim[i];
        const int b = tok >> 10, hw = tok & 1023;
        #pragma unroll
        for (int r = 0; r < 8; ++r) {
            int c = lane + r * 32;
            us[wid][c] = u[((size_t)(b * C_ + c) << 10) + hw];
        }
        __syncwarp();
        float best = 3.4e38f;
        int bi = KCODES;
        for (int t = 0; t < NTILE; ++t) {
            if (g_t1v[(size_t)t * NTOK + tok] > lim) continue;
            const int cb0 = t * CODT;
            const int c0 = cb0 + lane, c1 = cb0 + lane + 32;
            float d0 = 0.f, d1 = 0.f;
            #pragma unroll 8
            for (int k = 0; k < C_; ++k) {
                const float uv = us[wid][k];
                const float* row = g_codebookT + (size_t)k * KCODES + cb0;
                d0 = fmaf(uv, row[lane], d0);
                d1 = fmaf(uv, row[lane + 32], d1);
            }
            const float s0 = fmaf(-2.f, d0, g_cnorm[c0]);
            const float s1 = fmaf(-2.f, d1, g_cnorm[c1]);
            if (s0 < best || (s0 == best && c0 < bi)) { best = s0; bi = c0; }
            if (s1 < best || (s1 == best && c1 < bi)) { best = s1; bi = c1; }
        }
        #pragma unroll
        for (int off = 16; off > 0; off >>= 1) {
            float ov = __shfl_xor_sync(0xffffffffu, best, off);
            int oi = __shfl_xor_sync(0xffffffffu, bi, off);
            if (ov < best || (ov == best && oi < bi)) { best = ov; bi = oi; }
        }
        if (lane == 0) {
            g_idx[tok] = bi;
            out_idx[tok] = (float)bi;
        }
        __syncwarp();
    }
}

// ---------------------------------------------------------------------------
// K4: outputs. copy u, gather z_q, accumulate (z_q - u)^2 per (b,c)
// ---------------------------------------------------------------------------
__global__ void __launch_bounds__(256) epilogue_kernel(const float* __restrict__ u,
                                                       float* __restrict__ out) {
    __shared__ float col[KCODES];
    __shared__ float sred[256];
    const int c = blockIdx.x;
    const int b = blockIdx.y;
    const int tid = threadIdx.x;

    ((float4*)col)[tid] = ((const float4*)(g_codebookT + c * KCODES))[tid];
    __syncthreads();

    const long base = ((long)(b * C_ + c)) << 10;
    const float* ub = u + base;
    float* ou = out + OFF_U + base;
    float* oz = out + OFF_ZT + base;
    const int* ib = g_idx + (b << 10);

    float acc = 0.f;
    #pragma unroll
    for (int j = 0; j < 4; ++j) {
        int hw = tid + (j << 8);
        int i = ib[hw];
        float z = col[i];
        float uu = ub[hw];
        ou[hw] = uu;
        oz[hw] = z;
        float d = z - uu;
        acc = fmaf(d, d, acc);
    }
    sred[tid] = acc;
    __syncthreads();
    #pragma unroll
    for (int stride = 128; stride > 0; stride >>= 1) {
        if (tid < stride) sred[tid] += sred[tid + stride];
        __syncthreads();
    }
    if (tid == 0) g_partial[b * C_ + c] = sred[0];
}

// ---------------------------------------------------------------------------
// K5: final loss. vq = (1 + BETA) * mean((z_q - u)^2)
// ---------------------------------------------------------------------------
__global__ void __launch_bounds__(256) loss_kernel(float* __restrict__ out) {
    __shared__ float s[256];
    const int tid = threadIdx.x;
    float a = 0.f;
    for (int i = tid; i < B_ * C_; i += 256) a += g_partial[i];
    s[tid] = a;
    __syncthreads();
    #pragma unroll
    for (int stride = 128; stride > 0; stride >>= 1) {
        if (tid < stride) s[tid] += s[tid + stride];
        __syncthreads();
    }
    if (tid == 0)
        out[OFF_LOSS] = s[0] * (1.0f + BETA) / (float)SZ_U;
}

// ---------------------------------------------------------------------------
extern "C" void kernel_launch(void* const* d_in, const int* in_sizes, int n_in,
                              void* d_out, int out_size) {
    const float* u  = (const float*)d_in[0];
    const float* cb = (const float*)d_in[1];
    float* out = (float*)d_out;

    static bool attr_done = false;
    if (!attr_done) {
        cudaFuncSetAttribute(gemm_kernel,
                             cudaFuncAttributeMaxDynamicSharedMemorySize,
                             GEMM_SMEM);
        attr_done = true;
    }

    prep_kernel<<<KCODES, 256>>>(cb);
    gemm_kernel<<<dim3(NTILE, NTOK / TOKT), 256, GEMM_SMEM>>>(u, cb);
    reduce_kernel<<<NTOK / 256, 256>>>(out + OFF_IDX);
    rescue_kernel<<<256, 256>>>(u, out + OFF_IDX);
    epilogue_kernel<<<dim3(C_, B_), 256>>>(u, out);
    loss_kernel<<<1, 256>>>(out);
}

// round 9
// speedup vs baseline: 1.8896x; 1.5811x over previous
#include <cuda_runtime.h>
#include <cuda_bf16.h>
#include <cstdint>

// Problem constants
#define B_      32
#define C_      256
#define HW_     1024
#define NTOK    32768
#define KCODES  1024
#define BETA    0.25f

// Output layout (concatenated float32): u, z_train, vq_loss, indices
#define SZ_U    8388608
#define OFF_U   0
#define OFF_ZT  8388608
#define OFF_LOSS 16777216
#define OFF_IDX  16777217

// GEMM tiling
#define TOKT 256
#define CODT 64
#define NTILE (KCODES / CODT)   // 16
#define SA   264        // A smem stride: %32==8 -> conflict-free frags
#define SB   36         // B smem stride: %32==4 -> conflict-free frags

// Device scratch
__device__ float g_codebookT[C_ * KCODES];     // [c][code]
__device__ float g_cnorm[KCODES];
__device__ unsigned g_cmax_bits;               // max cnorm as float bits (atomicMax)
__device__ float g_unorm[NTOK];                // ||u_tok||
__device__ int   g_idx[NTOK];
__device__ float g_partial[B_ * C_];
__device__ float g_t1v[NTILE * NTOK];
__device__ int   g_t1i[NTILE * NTOK];
__device__ float g_t2v[NTILE * NTOK];

// ---------------------------------------------------------------------------
__device__ __forceinline__ float to_tf32f(float f) {
    uint32_t r;
    asm("cvt.rna.tf32.f32 %0, %1;" : "=r"(r) : "f"(f));
    return __uint_as_float(r);
}

__device__ __forceinline__ void mma_tf32(float* c, const uint32_t* a,
                                         const uint32_t* b) {
    asm volatile(
        "mma.sync.aligned.m16n8k8.row.col.f32.tf32.tf32.f32 "
        "{%0,%1,%2,%3}, {%4,%5,%6,%7}, {%8,%9}, {%0,%1,%2,%3};"
        : "+f"(c[0]), "+f"(c[1]), "+f"(c[2]), "+f"(c[3])
        : "r"(a[0]), "r"(a[1]), "r"(a[2]), "r"(a[3]), "r"(b[0]), "r"(b[1]));
}

__device__ __forceinline__ void upd_min2(float v, int i, float& m1, int& i1,
                                         float& m2) {
    if (v < m1) { m2 = m1; m1 = v; i1 = i; }
    else if (v < m2) { m2 = v; }
}

__device__ __forceinline__ void merge_min2(float& v1, int& i1, float& v2,
                                           float ov1, int oi1, float ov2) {
    if (ov1 < v1 || (ov1 == v1 && oi1 < i1)) {
        v2 = fminf(v1, ov2);
        v1 = ov1; i1 = oi1;
    } else {
        v2 = fminf(v2, ov1);
    }
}

// ---------------------------------------------------------------------------
// K0: codebook transpose + |c|^2 + cmax (atomicMax on positive-float bits)
// ---------------------------------------------------------------------------
__global__ void __launch_bounds__(256) prep_kernel(const float* __restrict__ cb) {
    __shared__ float s[256];
    int k = blockIdx.x;
    int c = threadIdx.x;
    float v = cb[k * C_ + c];
    g_codebookT[c * KCODES + k] = v;
    s[c] = v * v;
    __syncthreads();
    #pragma unroll
    for (int stride = 128; stride > 0; stride >>= 1) {
        if (c < stride) s[c] += s[c + stride];
        __syncthreads();
    }
    if (c == 0) {
        g_cnorm[k] = s[0];
        atomicMax(&g_cmax_bits, __float_as_uint(s[0]));  // cnorm >= 0: bit-monotone
    }
}

// K0b: per-token ||u||  grid (8, 32), 128 threads
__global__ void __launch_bounds__(128) unorm_kernel(const float* __restrict__ u) {
    const int b = blockIdx.y;
    const int hw = blockIdx.x * 128 + threadIdx.x;
    const float* up = u + (size_t)b * (C_ * HW_) + hw;
    float acc = 0.f;
    #pragma unroll 8
    for (int c = 0; c < C_; ++c) {
        float v = up[c * HW_];
        acc = fmaf(v, v, acc);
    }
    g_unorm[(b << 10) + hw] = sqrtf(acc) * 1.0002f;
}

// ---------------------------------------------------------------------------
// K1: single-pass tf32 tensor GEMM with fused per-tile argmin (R4's measured
// 149us kernel). grid (16 code-tiles, 128 token-tiles), 256 threads.
// ---------------------------------------------------------------------------
__global__ void __launch_bounds__(256, 2) gemm_kernel(const float* __restrict__ u,
                                                      const float* __restrict__ cb) {
    __shared__ float As[32 * SA];   // [k][tok]  33 KB
    __shared__ float Bs[CODT * SB]; // [code][k]  9 KB

    const int tid = threadIdx.x;
    const int w = tid >> 5, lane = tid & 31;
    const int g = lane >> 2, q = lane & 3;
    const int code0 = blockIdx.x * CODT;
    const int tok0 = blockIdx.y * TOKT;
    const int b = tok0 >> 10, hw0 = tok0 & 1023;
    const float* ub = u + (size_t)b * (C_ * HW_) + hw0;

    float acc[2][8][4];
    #pragma unroll
    for (int m = 0; m < 2; ++m)
        #pragma unroll
        for (int j = 0; j < 8; ++j)
            #pragma unroll
            for (int e = 0; e < 4; ++e) acc[m][j][e] = 0.f;

    const uint32_t* Au = (const uint32_t*)As;
    const uint32_t* Bu = (const uint32_t*)Bs;

    for (int kc = 0; kc < 8; ++kc) {
        const int k0 = kc * 32;
        // stage A: 32 k-rows x 256 tokens, cvt to tf32. 2048 f4, 8/thread
        #pragma unroll
        for (int p = 0; p < 8; ++p) {
            int f = tid + p * 256;
            int kr = f >> 6, t4 = (f & 63) << 2;
            float4 v = *(const float4*)&ub[(size_t)(k0 + kr) * HW_ + t4];
            v.x = to_tf32f(v.x);
            v.y = to_tf32f(v.y);
            v.z = to_tf32f(v.z);
            v.w = to_tf32f(v.w);
            *(float4*)&As[kr * SA + t4] = v;
        }
        // stage B: 64 codes x 32 k. 512 f4, 2/thread
        #pragma unroll
        for (int p = 0; p < 2; ++p) {
            int f = tid + p * 256;
            int cr = f >> 3, k4 = (f & 7) << 2;
            float4 v = *(const float4*)&cb[(size_t)(code0 + cr) * C_ + k0 + k4];
            v.x = to_tf32f(v.x);
            v.y = to_tf32f(v.y);
            v.z = to_tf32f(v.z);
            v.w = to_tf32f(v.w);
            *(float4*)&Bs[cr * SB + k4] = v;
        }
        __syncthreads();

        #pragma unroll
        for (int ks = 0; ks < 4; ++ks) {
            const int kb = ks * 8;
            uint32_t bf[8][2];
            #pragma unroll
            for (int j = 0; j < 8; ++j) {
                int row = (j * 8 + g) * SB + kb + q;
                bf[j][0] = Bu[row];
                bf[j][1] = Bu[row + 4];
            }
            #pragma unroll
            for (int m = 0; m < 2; ++m) {
                const int arow = w * 32 + m * 16 + g;
                uint32_t af[4];
                af[0] = Au[(kb + q) * SA + arow];
                af[1] = Au[(kb + q) * SA + arow + 8];
                af[2] = Au[(kb + q + 4) * SA + arow];
                af[3] = Au[(kb + q + 4) * SA + arow + 8];
                #pragma unroll
                for (int j = 0; j < 8; ++j) mma_tf32(acc[m][j], af, bf[j]);
            }
        }
        __syncthreads();
    }

    // fused per-tile argmin epilogue
    #pragma unroll
    for (int m = 0; m < 2; ++m) {
        float m1a = 3.4e38f, m2a = 3.4e38f; int i1a = 0;
        float m1b = 3.4e38f, m2b = 3.4e38f; int i1b = 0;
        #pragma unroll
        for (int j = 0; j < 8; ++j) {
            const int col = code0 + j * 8 + q * 2;
            const float cn0 = __ldg(&g_cnorm[col]);
            const float cn1 = __ldg(&g_cnorm[col + 1]);
            upd_min2(fmaf(-2.f, acc[m][j][0], cn0), col,     m1a, i1a, m2a);
            upd_min2(fmaf(-2.f, acc[m][j][1], cn1), col + 1, m1a, i1a, m2a);
            upd_min2(fmaf(-2.f, acc[m][j][2], cn0), col,     m1b, i1b, m2b);
            upd_min2(fmaf(-2.f, acc[m][j][3], cn1), col + 1, m1b, i1b, m2b);
        }
        #pragma unroll
        for (int off = 1; off <= 2; off <<= 1) {
            float ov1 = __shfl_xor_sync(0xffffffffu, m1a, off);
            int   oi1 = __shfl_xor_sync(0xffffffffu, i1a, off);
            float ov2 = __shfl_xor_sync(0xffffffffu, m2a, off);
            merge_min2(m1a, i1a, m2a, ov1, oi1, ov2);
            ov1 = __shfl_xor_sync(0xffffffffu, m1b, off);
            oi1 = __shfl_xor_sync(0xffffffffu, i1b, off);
            ov2 = __shfl_xor_sync(0xffffffffu, m2b, off);
            merge_min2(m1b, i1b, m2b, ov1, oi1, ov2);
        }
        if (q == 0) {
            const int t_lo = tok0 + w * 32 + m * 16 + g;
            const size_t base = (size_t)blockIdx.x * NTOK;
            g_t1v[base + t_lo] = m1a;
            g_t1i[base + t_lo] = i1a;
            g_t2v[base + t_lo] = m2a;
            g_t1v[base + t_lo + 8] = m1b;
            g_t1i[base + t_lo + 8] = i1b;
            g_t2v[base + t_lo + 8] = m2b;
        }
    }
}

// ---------------------------------------------------------------------------
// K2: fused reduce + verify. One WARP per token (4096 blocks x 8 warps).
// Merge 16 tile summaries; if the gap exceeds the rigorous tf32 margin,
// trust the tf32 argmin; else exact-fp32 rescan of candidate tiles
// (coalesced codebookT reads; superset of exact argmin is guaranteed).
// ---------------------------------------------------------------------------
__global__ void __launch_bounds__(256) verify_kernel(const float* __restrict__ u,
                                                     float* __restrict__ out_idx) {
    __shared__ float us[8][C_];
    const int wid = threadIdx.x >> 5, lane = threadIdx.x & 31;
    const int tok = blockIdx.x * 8 + wid;

    // merge 16 tile summaries across lanes 0..15
    float v1 = 3.4e38f, v2 = 3.4e38f;
    int i1 = 0;
    if (lane < NTILE) {
        const size_t p = (size_t)lane * NTOK + tok;
        v1 = g_t1v[p]; i1 = g_t1i[p]; v2 = g_t2v[p];
    }
    #pragma unroll
    for (int off = 8; off > 0; off >>= 1) {
        float ov1 = __shfl_xor_sync(0xffffffffu, v1, off);
        int   oi1 = __shfl_xor_sync(0xffffffffu, i1, off);
        float ov2 = __shfl_xor_sync(0xffffffffu, v2, off);
        merge_min2(v1, i1, v2, ov1, oi1, ov2);
    }
    const float m1 = __shfl_sync(0xffffffffu, v1, 0);
    const int   bi0 = __shfl_sync(0xffffffffu, i1, 0);
    const float m2 = __shfl_sync(0xffffffffu, v2, 0);

    const float cmax = sqrtf(__uint_as_float(g_cmax_bits)) * 1.0002f;
    const float margin = g_unorm[tok] * cmax * (1.02f / 512.f) + 2e-3f;

    if (m2 - m1 > margin) {
        if (lane == 0) {
            g_idx[tok] = bi0;
            out_idx[tok] = (float)bi0;
        }
        return;
    }

    // ambiguous: exact fp32 rescan of candidate tiles
    const float lim = m1 + margin;
    const int b = tok >> 10, hw = tok & 1023;
    #pragma unroll
    for (int r = 0; r < 8; ++r) {
        int c = lane + r * 32;
        us[wid][c] = u[((size_t)(b * C_ + c) << 10) + hw];
    }
    __syncwarp();

    float best = 3.4e38f;
    int bi = KCODES;
    for (int t = 0; t < NTILE; ++t) {
        if (g_t1v[(size_t)t * NTOK + tok] > lim) continue;
        const int cb0 = t * CODT;
        const int c0 = cb0 + lane, c1 = cb0 + lane + 32;
        float d0 = 0.f, d1 = 0.f;
        #pragma unroll 8
        for (int k = 0; k < C_; ++k) {
            const float uv = us[wid][k];
            const float* row = g_codebookT + (size_t)k * KCODES + cb0;
            d0 = fmaf(uv, row[lane], d0);
            d1 = fmaf(uv, row[lane + 32], d1);
        }
        const float s0 = fmaf(-2.f, d0, g_cnorm[c0]);
        const float s1 = fmaf(-2.f, d1, g_cnorm[c1]);
        if (s0 < best || (s0 == best && c0 < bi)) { best = s0; bi = c0; }
        if (s1 < best || (s1 == best && c1 < bi)) { best = s1; bi = c1; }
    }
    #pragma unroll
    for (int off = 16; off > 0; off >>= 1) {
        float ov = __shfl_xor_sync(0xffffffffu, best, off);
        int oi = __shfl_xor_sync(0xffffffffu, bi, off);
        if (ov < best || (ov == best && oi < bi)) { best = ov; bi = oi; }
    }
    if (lane == 0) {
        g_idx[tok] = bi;
        out_idx[tok] = (float)bi;
    }
}

// ---------------------------------------------------------------------------
// K3: outputs. copy u, gather z_q, accumulate (z_q - u)^2 per (b,c)
// ---------------------------------------------------------------------------
__global__ void __launch_bounds__(256) epilogue_kernel(const float* __restrict__ u,
                                                       float* __restrict__ out) {
    __shared__ float col[KCODES];
    __shared__ float sred[256];
    const int c = blockIdx.x;
    const int b = blockIdx.y;
    const int tid = threadIdx.x;

    ((float4*)col)[tid] = ((const float4*)(g_codebookT + c * KCODES))[tid];
    __syncthreads();

    const long base = ((long)(b * C_ + c)) << 10;
    const float* ub = u + base;
    float* ou = out + OFF_U + base;
    float* oz = out + OFF_ZT + base;
    const int* ib = g_idx + (b << 10);

    float acc = 0.f;
    #pragma unroll
    for (int j = 0; j < 4; ++j) {
        int hw = tid + (j << 8);
        int i = ib[hw];
        float z = col[i];
        float uu = ub[hw];
        ou[hw] = uu;
        oz[hw] = z;
        float d = z - uu;
        acc = fmaf(d, d, acc);
    }
    sred[tid] = acc;
    __syncthreads();
    #pragma unroll
    for (int stride = 128; stride > 0; stride >>= 1) {
        if (tid < stride) sred[tid] += sred[tid + stride];
        __syncthreads();
    }
    if (tid == 0) g_partial[b * C_ + c] = sred[0];
}

// ---------------------------------------------------------------------------
// K4: final loss. vq = (1 + BETA) * mean((z_q - u)^2)
// ---------------------------------------------------------------------------
__global__ void __launch_bounds__(256) loss_kernel(float* __restrict__ out) {
    __shared__ float s[256];
    const int tid = threadIdx.x;
    float a = 0.f;
    for (int i = tid; i < B_ * C_; i += 256) a += g_partial[i];
    s[tid] = a;
    __syncthreads();
    #pragma unroll
    for (int stride = 128; stride > 0; stride >>= 1) {
        if (tid < stride) s[tid] += s[tid + stride];
        __syncthreads();
    }
    if (tid == 0)
        out[OFF_LOSS] = s[0] * (1.0f + BETA) / (float)SZ_U;
}

// ---------------------------------------------------------------------------
extern "C" void kernel_launch(void* const* d_in, const int* in_sizes, int n_in,
                              void* d_out, int out_size) {
    const float* u  = (const float*)d_in[0];
    const float* cb = (const float*)d_in[1];
    float* out = (float*)d_out;

    prep_kernel<<<KCODES, 256>>>(cb);
    unorm_kernel<<<dim3(8, B_), 128>>>(u);
    gemm_kernel<<<dim3(NTILE, NTOK / TOKT), 256>>>(u, cb);
    verify_kernel<<<NTOK / 8, 256>>>(u, out + OFF_IDX);
    epilogue_kernel<<<dim3(C_, B_), 256>>>(u, out);
    loss_kernel<<<1, 256>>>(out);
}

// round 10
// speedup vs baseline: 2.0686x; 1.0947x over previous
#include <cuda_runtime.h>
#include <cuda_bf16.h>
#include <cstdint>

// Problem constants
#define B_      32
#define C_      256
#define HW_     1024
#define NTOK    32768
#define KCODES  1024
#define BETA    0.25f

// Output layout (concatenated float32): u, z_train, vq_loss, indices
#define SZ_U    8388608
#define OFF_U   0
#define OFF_ZT  8388608
#define OFF_LOSS 16777216
#define OFF_IDX  16777217

// GEMM tiling
#define TOKT 256
#define CODT 64
#define NTILE (KCODES / CODT)   // 16
#define SA   264        // A smem stride: %32==8 -> conflict-free frags
#define SB   36         // B smem stride: %32==4 -> conflict-free frags

// Device scratch
__device__ float g_codebookT[C_ * KCODES];     // [c][code]
__device__ float g_cnorm[KCODES];
__device__ unsigned g_cmax_bits;               // max cnorm bits (atomicMax)
__device__ float g_unorm[NTOK];                // ||u_tok||
__device__ int   g_idx[NTOK];
__device__ float g_partial[B_ * C_];
__device__ float g_t1v[NTILE * NTOK];
__device__ int   g_t1i[NTILE * NTOK];
__device__ float g_t2v[NTILE * NTOK];

// ---------------------------------------------------------------------------
__device__ __forceinline__ float to_tf32f(float f) {
    uint32_t r;
    asm("cvt.rna.tf32.f32 %0, %1;" : "=r"(r) : "f"(f));
    return __uint_as_float(r);
}

__device__ __forceinline__ void mma_tf32(float* c, const uint32_t* a,
                                         const uint32_t* b) {
    asm volatile(
        "mma.sync.aligned.m16n8k8.row.col.f32.tf32.tf32.f32 "
        "{%0,%1,%2,%3}, {%4,%5,%6,%7}, {%8,%9}, {%0,%1,%2,%3};"
        : "+f"(c[0]), "+f"(c[1]), "+f"(c[2]), "+f"(c[3])
        : "r"(a[0]), "r"(a[1]), "r"(a[2]), "r"(a[3]), "r"(b[0]), "r"(b[1]));
}

__device__ __forceinline__ void upd_min2(float v, int i, float& m1, int& i1,
                                         float& m2) {
    if (v < m1) { m2 = m1; m1 = v; i1 = i; }
    else if (v < m2) { m2 = v; }
}

__device__ __forceinline__ void merge_min2(float& v1, int& i1, float& v2,
                                           float ov1, int oi1, float ov2) {
    if (ov1 < v1 || (ov1 == v1 && oi1 < i1)) {
        v2 = fminf(v1, ov2);
        v1 = ov1; i1 = oi1;
    } else {
        v2 = fminf(v2, ov1);
    }
}

// ---------------------------------------------------------------------------
// K0: codebook transpose + |c|^2 + cmax
// ---------------------------------------------------------------------------
__global__ void __launch_bounds__(256) prep_kernel(const float* __restrict__ cb) {
    __shared__ float s[256];
    int k = blockIdx.x;
    int c = threadIdx.x;
    float v = cb[k * C_ + c];
    g_codebookT[c * KCODES + k] = v;
    s[c] = v * v;
    __syncthreads();
    #pragma unroll
    for (int stride = 128; stride > 0; stride >>= 1) {
        if (c < stride) s[c] += s[c + stride];
        __syncthreads();
    }
    if (c == 0) {
        g_cnorm[k] = s[0];
        atomicMax(&g_cmax_bits, __float_as_uint(s[0]));
    }
}

// K0b: per-token ||u||
__global__ void __launch_bounds__(128) unorm_kernel(const float* __restrict__ u) {
    const int b = blockIdx.y;
    const int hw = blockIdx.x * 128 + threadIdx.x;
    const float* up = u + (size_t)b * (C_ * HW_) + hw;
    float acc = 0.f;
    #pragma unroll 8
    for (int c = 0; c < C_; ++c) {
        float v = up[c * HW_];
        acc = fmaf(v, v, acc);
    }
    g_unorm[(b << 10) + hw] = sqrtf(acc) * 1.0002f;
}

// ---------------------------------------------------------------------------
// K1: single-pass tf32 tensor GEMM with fused per-tile argmin (unchanged).
// ---------------------------------------------------------------------------
__global__ void __launch_bounds__(256, 2) gemm_kernel(const float* __restrict__ u,
                                                      const float* __restrict__ cb) {
    __shared__ float As[32 * SA];
    __shared__ float Bs[CODT * SB];

    const int tid = threadIdx.x;
    const int w = tid >> 5, lane = tid & 31;
    const int g = lane >> 2, q = lane & 3;
    const int code0 = blockIdx.x * CODT;
    const int tok0 = blockIdx.y * TOKT;
    const int b = tok0 >> 10, hw0 = tok0 & 1023;
    const float* ub = u + (size_t)b * (C_ * HW_) + hw0;

    float acc[2][8][4];
    #pragma unroll
    for (int m = 0; m < 2; ++m)
        #pragma unroll
        for (int j = 0; j < 8; ++j)
            #pragma unroll
            for (int e = 0; e < 4; ++e) acc[m][j][e] = 0.f;

    const uint32_t* Au = (const uint32_t*)As;
    const uint32_t* Bu = (const uint32_t*)Bs;

    for (int kc = 0; kc < 8; ++kc) {
        const int k0 = kc * 32;
        #pragma unroll
        for (int p = 0; p < 8; ++p) {
            int f = tid + p * 256;
            int kr = f >> 6, t4 = (f & 63) << 2;
            float4 v = *(const float4*)&ub[(size_t)(k0 + kr) * HW_ + t4];
            v.x = to_tf32f(v.x);
            v.y = to_tf32f(v.y);
            v.z = to_tf32f(v.z);
            v.w = to_tf32f(v.w);
            *(float4*)&As[kr * SA + t4] = v;
        }
        #pragma unroll
        for (int p = 0; p < 2; ++p) {
            int f = tid + p * 256;
            int cr = f >> 3, k4 = (f & 7) << 2;
            float4 v = *(const float4*)&cb[(size_t)(code0 + cr) * C_ + k0 + k4];
            v.x = to_tf32f(v.x);
            v.y = to_tf32f(v.y);
            v.z = to_tf32f(v.z);
            v.w = to_tf32f(v.w);
            *(float4*)&Bs[cr * SB + k4] = v;
        }
        __syncthreads();

        #pragma unroll
        for (int ks = 0; ks < 4; ++ks) {
            const int kb = ks * 8;
            uint32_t bf[8][2];
            #pragma unroll
            for (int j = 0; j < 8; ++j) {
                int row = (j * 8 + g) * SB + kb + q;
                bf[j][0] = Bu[row];
                bf[j][1] = Bu[row + 4];
            }
            #pragma unroll
            for (int m = 0; m < 2; ++m) {
                const int arow = w * 32 + m * 16 + g;
                uint32_t af[4];
                af[0] = Au[(kb + q) * SA + arow];
                af[1] = Au[(kb + q) * SA + arow + 8];
                af[2] = Au[(kb + q + 4) * SA + arow];
                af[3] = Au[(kb + q + 4) * SA + arow + 8];
                #pragma unroll
                for (int j = 0; j < 8; ++j) mma_tf32(acc[m][j], af, bf[j]);
            }
        }
        __syncthreads();
    }

    #pragma unroll
    for (int m = 0; m < 2; ++m) {
        float m1a = 3.4e38f, m2a = 3.4e38f; int i1a = 0;
        float m1b = 3.4e38f, m2b = 3.4e38f; int i1b = 0;
        #pragma unroll
        for (int j = 0; j < 8; ++j) {
            const int col = code0 + j * 8 + q * 2;
            const float cn0 = __ldg(&g_cnorm[col]);
            const float cn1 = __ldg(&g_cnorm[col + 1]);
            upd_min2(fmaf(-2.f, acc[m][j][0], cn0), col,     m1a, i1a, m2a);
            upd_min2(fmaf(-2.f, acc[m][j][1], cn1), col + 1, m1a, i1a, m2a);
            upd_min2(fmaf(-2.f, acc[m][j][2], cn0), col,     m1b, i1b, m2b);
            upd_min2(fmaf(-2.f, acc[m][j][3], cn1), col + 1, m1b, i1b, m2b);
        }
        #pragma unroll
        for (int off = 1; off <= 2; off <<= 1) {
            float ov1 = __shfl_xor_sync(0xffffffffu, m1a, off);
            int   oi1 = __shfl_xor_sync(0xffffffffu, i1a, off);
            float ov2 = __shfl_xor_sync(0xffffffffu, m2a, off);
            merge_min2(m1a, i1a, m2a, ov1, oi1, ov2);
            ov1 = __shfl_xor_sync(0xffffffffu, m1b, off);
            oi1 = __shfl_xor_sync(0xffffffffu, i1b, off);
            ov2 = __shfl_xor_sync(0xffffffffu, m2b, off);
            merge_min2(m1b, i1b, m2b, ov1, oi1, ov2);
        }
        if (q == 0) {
            const int t_lo = tok0 + w * 32 + m * 16 + g;
            const size_t base = (size_t)blockIdx.x * NTOK;
            g_t1v[base + t_lo] = m1a;
            g_t1i[base + t_lo] = i1a;
            g_t2v[base + t_lo] = m2a;
            g_t1v[base + t_lo + 8] = m1b;
            g_t1i[base + t_lo + 8] = i1b;
            g_t2v[base + t_lo + 8] = m2b;
        }
    }
}

// ---------------------------------------------------------------------------
// K2: fused reduce + verify. Warp per token. Rescue v2: per pass, each 8-lane
// group streams one code row of cb with float4 loads (coalesced, high MLP),
// 3-level shfl reduce over the k-partition.
// ---------------------------------------------------------------------------
__global__ void __launch_bounds__(256) verify_kernel(const float* __restrict__ u,
                                                     const float* __restrict__ cb,
                                                     float* __restrict__ out_idx) {
    __shared__ __align__(16) float us[8][C_];
    const int wid = threadIdx.x >> 5, lane = threadIdx.x & 31;
    const int tok = blockIdx.x * 8 + wid;

    // merge 16 tile summaries across lanes 0..15
    float v1 = 3.4e38f, v2 = 3.4e38f;
    int i1 = 0;
    if (lane < NTILE) {
        const size_t p = (size_t)lane * NTOK + tok;
        v1 = g_t1v[p]; i1 = g_t1i[p]; v2 = g_t2v[p];
    }
    #pragma unroll
    for (int off = 8; off > 0; off >>= 1) {
        float ov1 = __shfl_xor_sync(0xffffffffu, v1, off);
        int   oi1 = __shfl_xor_sync(0xffffffffu, i1, off);
        float ov2 = __shfl_xor_sync(0xffffffffu, v2, off);
        merge_min2(v1, i1, v2, ov1, oi1, ov2);
    }
    const float m1 = __shfl_sync(0xffffffffu, v1, 0);
    const int   bi0 = __shfl_sync(0xffffffffu, i1, 0);
    const float m2 = __shfl_sync(0xffffffffu, v2, 0);

    const float cmax = sqrtf(__uint_as_float(g_cmax_bits)) * 1.0002f;
    const float margin = g_unorm[tok] * cmax * (1.02f / 512.f) + 2e-3f;

    if (m2 - m1 > margin) {
        if (lane == 0) {
            g_idx[tok] = bi0;
            out_idx[tok] = (float)bi0;
        }
        return;
    }

    // ambiguous: exact fp32 rescan of candidate tiles
    const float lim = m1 + margin;
    const int b = tok >> 10, hw = tok & 1023;
    #pragma unroll
    for (int r = 0; r < 8; ++r) {
        int c = lane + r * 32;
        us[wid][c] = u[((size_t)(b * C_ + c) << 10) + hw];
    }
    __syncwarp();

    const int group = lane >> 3;        // 0..3: which code in the 4-pack
    const int ks = (lane & 7) << 2;     // k offset base (floats)
    float4 uu[8];
    #pragma unroll
    for (int i = 0; i < 8; ++i)
        uu[i] = *(const float4*)&us[wid][ks + i * 32];

    float best = 3.4e38f;
    int bi = KCODES;
    for (int t = 0; t < NTILE; ++t) {
        if (g_t1v[(size_t)t * NTOK + tok] > lim) continue;
        const int cb0 = t * CODT;
        #pragma unroll 4
        for (int p = 0; p < 16; ++p) {
            const int cg = cb0 + p * 4 + group;
            const float* cp = cb + (size_t)cg * C_ + ks;
            float d = 0.f;
            #pragma unroll
            for (int i = 0; i < 8; ++i) {
                float4 x = *(const float4*)&cp[i * 32];
                d = fmaf(x.x, uu[i].x, d);
                d = fmaf(x.y, uu[i].y, d);
                d = fmaf(x.z, uu[i].z, d);
                d = fmaf(x.w, uu[i].w, d);
            }
            d += __shfl_xor_sync(0xffffffffu, d, 1);
            d += __shfl_xor_sync(0xffffffffu, d, 2);
            d += __shfl_xor_sync(0xffffffffu, d, 4);
            const float s = fmaf(-2.f, d, __ldg(&g_cnorm[cg]));
            if (s < best || (s == best && cg < bi)) { best = s; bi = cg; }
        }
    }
    #pragma unroll
    for (int off = 16; off > 0; off >>= 1) {
        float ov = __shfl_xor_sync(0xffffffffu, best, off);
        int oi = __shfl_xor_sync(0xffffffffu, bi, off);
        if (ov < best || (ov == best && oi < bi)) { best = ov; bi = oi; }
    }
    if (lane == 0) {
        g_idx[tok] = bi;
        out_idx[tok] = (float)bi;
    }
}

// ---------------------------------------------------------------------------
// K3: outputs. copy u, gather z_q, accumulate (z_q - u)^2 per (b,c)
// ---------------------------------------------------------------------------
__global__ void __launch_bounds__(256) epilogue_kernel(const float* __restrict__ u,
                                                       float* __restrict__ out) {
    __shared__ float col[KCODES];
    __shared__ float sred[256];
    const int c = blockIdx.x;
    const int b = blockIdx.y;
    const int tid = threadIdx.x;

    ((float4*)col)[tid] = ((const float4*)(g_codebookT + c * KCODES))[tid];
    __syncthreads();

    const long base = ((long)(b * C_ + c)) << 10;
    const float* ub = u + base;
    float* ou = out + OFF_U + base;
    float* oz = out + OFF_ZT + base;
    const int* ib = g_idx + (b << 10);

    float acc = 0.f;
    #pragma unroll
    for (int j = 0; j < 4; ++j) {
        int hw = tid + (j << 8);
        int i = ib[hw];
        float z = col[i];
        float uu = ub[hw];
        ou[hw] = uu;
        oz[hw] = z;
        float d = z - uu;
        acc = fmaf(d, d, acc);
    }
    sred[tid] = acc;
    __syncthreads();
    #pragma unroll
    for (int stride = 128; stride > 0; stride >>= 1) {
        if (tid < stride) sred[tid] += sred[tid + stride];
        __syncthreads();
    }
    if (tid == 0) g_partial[b * C_ + c] = sred[0];
}

// ---------------------------------------------------------------------------
// K4: final loss. vq = (1 + BETA) * mean((z_q - u)^2)
// ---------------------------------------------------------------------------
__global__ void __launch_bounds__(256) loss_kernel(float* __restrict__ out) {
    __shared__ float s[256];
    const int tid = threadIdx.x;
    float a = 0.f;
    for (int i = tid; i < B_ * C_; i += 256) a += g_partial[i];
    s[tid] = a;
    __syncthreads();
    #pragma unroll
    for (int stride = 128; stride > 0; stride >>= 1) {
        if (tid < stride) s[tid] += s[tid + stride];
        __syncthreads();
    }
    if (tid == 0)
        out[OFF_LOSS] = s[0] * (1.0f + BETA) / (float)SZ_U;
}

// ---------------------------------------------------------------------------
extern "C" void kernel_launch(void* const* d_in, const int* in_sizes, int n_in,
                              void* d_out, int out_size) {
    const float* u  = (const float*)d_in[0];
    const float* cb = (const float*)d_in[1];
    float* out = (float*)d_out;

    prep_kernel<<<KCODES, 256>>>(cb);
    unorm_kernel<<<dim3(8, B_), 128>>>(u);
    gemm_kernel<<<dim3(NTILE, NTOK / TOKT), 256>>>(u, cb);
    verify_kernel<<<NTOK / 8, 256>>>(u, cb, out + OFF_IDX);
    epilogue_kernel<<<dim3(C_, B_), 256>>>(u, out);
    loss_kernel<<<1, 256>>>(out);
}

// round 11
// speedup vs baseline: 2.2416x; 1.0837x over previous
#include <cuda_runtime.h>
#include <cuda_bf16.h>
#include <cstdint>

// Problem constants
#define B_      32
#define C_      256
#define HW_     1024
#define NTOK    32768
#define KCODES  1024
#define BETA    0.25f

// Output layout (concatenated float32): u, z_train, vq_loss, indices
#define SZ_U    8388608
#define OFF_U   0
#define OFF_ZT  8388608
#define OFF_LOSS 16777216
#define OFF_IDX  16777217

// GEMM tiling
#define TOKT 256
#define CODT 64
#define NTILE (KCODES / CODT)   // 16
#define SA   264        // A smem stride: %32==8 -> conflict-free frags
#define SB   36         // B smem stride: %32==4 -> conflict-free frags

// Device scratch
__device__ float g_codebookT[C_ * KCODES];     // [c][code]
__device__ float g_cnorm[KCODES];
__device__ unsigned g_cmax_bits;
__device__ float g_unorm[NTOK];
__device__ int   g_idx[NTOK];
__device__ float g_partial[B_ * C_];
// packed per-(token, tile) summary: {m1, m2, idx_bits, pad}
__device__ __align__(16) float4 g_sum[NTOK * NTILE];   // 8 MB
__device__ int   g_nambig;
__device__ int   g_ambig[NTOK];
__device__ float g_lim[NTOK];

// ---------------------------------------------------------------------------
__device__ __forceinline__ float to_tf32f(float f) {
    uint32_t r;
    asm("cvt.rna.tf32.f32 %0, %1;" : "=r"(r) : "f"(f));
    return __uint_as_float(r);
}

__device__ __forceinline__ void mma_tf32(float* c, const uint32_t* a,
                                         const uint32_t* b) {
    asm volatile(
        "mma.sync.aligned.m16n8k8.row.col.f32.tf32.tf32.f32 "
        "{%0,%1,%2,%3}, {%4,%5,%6,%7}, {%8,%9}, {%0,%1,%2,%3};"
        : "+f"(c[0]), "+f"(c[1]), "+f"(c[2]), "+f"(c[3])
        : "r"(a[0]), "r"(a[1]), "r"(a[2]), "r"(a[3]), "r"(b[0]), "r"(b[1]));
}

__device__ __forceinline__ void upd_min2(float v, int i, float& m1, int& i1,
                                         float& m2) {
    if (v < m1) { m2 = m1; m1 = v; i1 = i; }
    else if (v < m2) { m2 = v; }
}

__device__ __forceinline__ void merge_min2(float& v1, int& i1, float& v2,
                                           float ov1, int oi1, float ov2) {
    if (ov1 < v1 || (ov1 == v1 && oi1 < i1)) {
        v2 = fminf(v1, ov2);
        v1 = ov1; i1 = oi1;
    } else {
        v2 = fminf(v2, ov1);
    }
}

// ---------------------------------------------------------------------------
// K0: codebook transpose + |c|^2 + cmax + zero ambig counter
// ---------------------------------------------------------------------------
__global__ void __launch_bounds__(256) prep_kernel(const float* __restrict__ cb) {
    __shared__ float s[256];
    int k = blockIdx.x;
    int c = threadIdx.x;
    if (k == 0 && c == 0) g_nambig = 0;
    float v = cb[k * C_ + c];
    g_codebookT[c * KCODES + k] = v;
    s[c] = v * v;
    __syncthreads();
    #pragma unroll
    for (int stride = 128; stride > 0; stride >>= 1) {
        if (c < stride) s[c] += s[c + stride];
        __syncthreads();
    }
    if (c == 0) {
        g_cnorm[k] = s[0];
        atomicMax(&g_cmax_bits, __float_as_uint(s[0]));
    }
}

// K0b: per-token ||u||
__global__ void __launch_bounds__(128) unorm_kernel(const float* __restrict__ u) {
    const int b = blockIdx.y;
    const int hw = blockIdx.x * 128 + threadIdx.x;
    const float* up = u + (size_t)b * (C_ * HW_) + hw;
    float acc = 0.f;
    #pragma unroll 8
    for (int c = 0; c < C_; ++c) {
        float v = up[c * HW_];
        acc = fmaf(v, v, acc);
    }
    g_unorm[(b << 10) + hw] = sqrtf(acc) * 1.0002f;
}

// ---------------------------------------------------------------------------
// K1: single-pass tf32 tensor GEMM with fused per-tile argmin.
// Summary now stored packed at [token][tile] for coalesced reduce.
// ---------------------------------------------------------------------------
__global__ void __launch_bounds__(256, 2) gemm_kernel(const float* __restrict__ u,
                                                      const float* __restrict__ cb) {
    __shared__ float As[32 * SA];
    __shared__ float Bs[CODT * SB];

    const int tid = threadIdx.x;
    const int w = tid >> 5, lane = tid & 31;
    const int g = lane >> 2, q = lane & 3;
    const int code0 = blockIdx.x * CODT;
    const int tok0 = blockIdx.y * TOKT;
    const int b = tok0 >> 10, hw0 = tok0 & 1023;
    const float* ub = u + (size_t)b * (C_ * HW_) + hw0;

    float acc[2][8][4];
    #pragma unroll
    for (int m = 0; m < 2; ++m)
        #pragma unroll
        for (int j = 0; j < 8; ++j)
            #pragma unroll
            for (int e = 0; e < 4; ++e) acc[m][j][e] = 0.f;

    const uint32_t* Au = (const uint32_t*)As;
    const uint32_t* Bu = (const uint32_t*)Bs;

    for (int kc = 0; kc < 8; ++kc) {
        const int k0 = kc * 32;
        #pragma unroll
        for (int p = 0; p < 8; ++p) {
            int f = tid + p * 256;
            int kr = f >> 6, t4 = (f & 63) << 2;
            float4 v = *(const float4*)&ub[(size_t)(k0 + kr) * HW_ + t4];
            v.x = to_tf32f(v.x);
            v.y = to_tf32f(v.y);
            v.z = to_tf32f(v.z);
            v.w = to_tf32f(v.w);
            *(float4*)&As[kr * SA + t4] = v;
        }
        #pragma unroll
        for (int p = 0; p < 2; ++p) {
            int f = tid + p * 256;
            int cr = f >> 3, k4 = (f & 7) << 2;
            float4 v = *(const float4*)&cb[(size_t)(code0 + cr) * C_ + k0 + k4];
            v.x = to_tf32f(v.x);
            v.y = to_tf32f(v.y);
            v.z = to_tf32f(v.z);
            v.w = to_tf32f(v.w);
            *(float4*)&Bs[cr * SB + k4] = v;
        }
        __syncthreads();

        #pragma unroll
        for (int ks = 0; ks < 4; ++ks) {
            const int kb = ks * 8;
            uint32_t bf[8][2];
            #pragma unroll
            for (int j = 0; j < 8; ++j) {
                int row = (j * 8 + g) * SB + kb + q;
                bf[j][0] = Bu[row];
                bf[j][1] = Bu[row + 4];
            }
            #pragma unroll
            for (int m = 0; m < 2; ++m) {
                const int arow = w * 32 + m * 16 + g;
                uint32_t af[4];
                af[0] = Au[(kb + q) * SA + arow];
                af[1] = Au[(kb + q) * SA + arow + 8];
                af[2] = Au[(kb + q + 4) * SA + arow];
                af[3] = Au[(kb + q + 4) * SA + arow + 8];
                #pragma unroll
                for (int j = 0; j < 8; ++j) mma_tf32(acc[m][j], af, bf[j]);
            }
        }
        __syncthreads();
    }

    #pragma unroll
    for (int m = 0; m < 2; ++m) {
        float m1a = 3.4e38f, m2a = 3.4e38f; int i1a = 0;
        float m1b = 3.4e38f, m2b = 3.4e38f; int i1b = 0;
        #pragma unroll
        for (int j = 0; j < 8; ++j) {
            const int col = code0 + j * 8 + q * 2;
            const float cn0 = __ldg(&g_cnorm[col]);
            const float cn1 = __ldg(&g_cnorm[col + 1]);
            upd_min2(fmaf(-2.f, acc[m][j][0], cn0), col,     m1a, i1a, m2a);
            upd_min2(fmaf(-2.f, acc[m][j][1], cn1), col + 1, m1a, i1a, m2a);
            upd_min2(fmaf(-2.f, acc[m][j][2], cn0), col,     m1b, i1b, m2b);
            upd_min2(fmaf(-2.f, acc[m][j][3], cn1), col + 1, m1b, i1b, m2b);
        }
        #pragma unroll
        for (int off = 1; off <= 2; off <<= 1) {
            float ov1 = __shfl_xor_sync(0xffffffffu, m1a, off);
            int   oi1 = __shfl_xor_sync(0xffffffffu, i1a, off);
            float ov2 = __shfl_xor_sync(0xffffffffu, m2a, off);
            merge_min2(m1a, i1a, m2a, ov1, oi1, ov2);
            ov1 = __shfl_xor_sync(0xffffffffu, m1b, off);
            oi1 = __shfl_xor_sync(0xffffffffu, i1b, off);
            ov2 = __shfl_xor_sync(0xffffffffu, m2b, off);
            merge_min2(m1b, i1b, m2b, ov1, oi1, ov2);
        }
        if (q == 0) {
            const int t_lo = tok0 + w * 32 + m * 16 + g;
            g_sum[(size_t)t_lo * NTILE + blockIdx.x] =
                make_float4(m1a, m2a, __int_as_float(i1a), 0.f);
            g_sum[(size_t)(t_lo + 8) * NTILE + blockIdx.x] =
                make_float4(m1b, m2b, __int_as_float(i1b), 0.f);
        }
    }
}

// ---------------------------------------------------------------------------
// K2: reduce. Thread per token; 16 contiguous float4 summary reads; margin
// check; build ambiguous worklist.
// ---------------------------------------------------------------------------
__global__ void __launch_bounds__(256) reduce_kernel(float* __restrict__ out_idx) {
    const int tok = blockIdx.x * 256 + threadIdx.x;
    const float4* sp = g_sum + (size_t)tok * NTILE;
    float m1 = 3.4e38f, m2 = 3.4e38f;
    int i1 = 0;
    #pragma unroll
    for (int t = 0; t < NTILE; ++t) {
        float4 s = sp[t];
        merge_min2(m1, i1, m2, s.x, __float_as_int(s.z), s.y);
    }
    g_idx[tok] = i1;
    out_idx[tok] = (float)i1;
    const float cmax = sqrtf(__uint_as_float(g_cmax_bits)) * 1.0002f;
    const float margin = g_unorm[tok] * cmax * (1.02f / 512.f) + 2e-3f;
    if (m2 - m1 <= margin) {
        int slot = atomicAdd(&g_nambig, 1);
        g_ambig[slot] = tok;
        g_lim[slot] = m1 + margin;
    }
}

// ---------------------------------------------------------------------------
// K3: worklist rescue. Warp per entry, grid-stride. Per candidate tile,
// each 8-lane group streams one cb row with float4 loads; shfl k-reduce.
// ---------------------------------------------------------------------------
__global__ void __launch_bounds__(256) rescue_kernel(const float* __restrict__ u,
                                                     const float* __restrict__ cb,
                                                     float* __restrict__ out_idx) {
    __shared__ __align__(16) float us[8][C_];
    const int wid = threadIdx.x >> 5, lane = threadIdx.x & 31;
    const int gw = blockIdx.x * 8 + wid;
    const int nwarps = gridDim.x * 8;
    const int n = g_nambig;

    const int group = lane >> 3;
    const int ks = (lane & 7) << 2;

    for (int i = gw; i < n; i += nwarps) {
        const int tok = g_ambig[i];
        const float lim = g_lim[i];
        const int b = tok >> 10, hw = tok & 1023;
        #pragma unroll
        for (int r = 0; r < 8; ++r) {
            int c = lane + r * 32;
            us[wid][c] = u[((size_t)(b * C_ + c) << 10) + hw];
        }
        __syncwarp();
        float4 uu[8];
        #pragma unroll
        for (int r = 0; r < 8; ++r)
            uu[r] = *(const float4*)&us[wid][ks + r * 32];

        const float4* sp = g_sum + (size_t)tok * NTILE;
        float best = 3.4e38f;
        int bi = KCODES;
        for (int t = 0; t < NTILE; ++t) {
            if (sp[t].x > lim) continue;
            const int cb0 = t * CODT;
            #pragma unroll 4
            for (int p = 0; p < 16; ++p) {
                const int cg = cb0 + p * 4 + group;
                const float* cp = cb + (size_t)cg * C_ + ks;
                float d = 0.f;
                #pragma unroll
                for (int r = 0; r < 8; ++r) {
                    float4 x = *(const float4*)&cp[r * 32];
                    d = fmaf(x.x, uu[r].x, d);
                    d = fmaf(x.y, uu[r].y, d);
                    d = fmaf(x.z, uu[r].z, d);
                    d = fmaf(x.w, uu[r].w, d);
                }
                d += __shfl_xor_sync(0xffffffffu, d, 1);
                d += __shfl_xor_sync(0xffffffffu, d, 2);
                d += __shfl_xor_sync(0xffffffffu, d, 4);
                const float s = fmaf(-2.f, d, __ldg(&g_cnorm[cg]));
                if (s < best || (s == best && cg < bi)) { best = s; bi = cg; }
            }
        }
        #pragma unroll
        for (int off = 16; off > 0; off >>= 1) {
            float ov = __shfl_xor_sync(0xffffffffu, best, off);
            int oi = __shfl_xor_sync(0xffffffffu, bi, off);
            if (ov < best || (ov == best && oi < bi)) { best = ov; bi = oi; }
        }
        if (lane == 0) {
            g_idx[tok] = bi;
            out_idx[tok] = (float)bi;
        }
        __syncwarp();
    }
}

// ---------------------------------------------------------------------------
// K4: outputs. copy u, gather z_q, accumulate (z_q - u)^2 per (b,c)
// ---------------------------------------------------------------------------
__global__ void __launch_bounds__(256) epilogue_kernel(const float* __restrict__ u,
                                                       float* __restrict__ out) {
    __shared__ float col[KCODES];
    __shared__ float sred[256];
    const int c = blockIdx.x;
    const int b = blockIdx.y;
    const int tid = threadIdx.x;

    ((float4*)col)[tid] = ((const float4*)(g_codebookT + c * KCODES))[tid];
    __syncthreads();

    const long base = ((long)(b * C_ + c)) << 10;
    const float* ub = u + base;
    float* ou = out + OFF_U + base;
    float* oz = out + OFF_ZT + base;
    const int* ib = g_idx + (b << 10);

    float acc = 0.f;
    #pragma unroll
    for (int j = 0; j < 4; ++j) {
        int hw = tid + (j << 8);
        int i = ib[hw];
        float z = col[i];
        float uu = ub[hw];
        ou[hw] = uu;
        oz[hw] = z;
        float d = z - uu;
        acc = fmaf(d, d, acc);
    }
    sred[tid] = acc;
    __syncthreads();
    #pragma unroll
    for (int stride = 128; stride > 0; stride >>= 1) {
        if (tid < stride) sred[tid] += sred[tid + stride];
        __syncthreads();
    }
    if (tid == 0) g_partial[b * C_ + c] = sred[0];
}

// ---------------------------------------------------------------------------
// K5: final loss. vq = (1 + BETA) * mean((z_q - u)^2)
// ---------------------------------------------------------------------------
__global__ void __launch_bounds__(256) loss_kernel(float* __restrict__ out) {
    __shared__ float s[256];
    const int tid = threadIdx.x;
    float a = 0.f;
    for (int i = tid; i < B_ * C_; i += 256) a += g_partial[i];
    s[tid] = a;
    __syncthreads();
    #pragma unroll
    for (int stride = 128; stride > 0; stride >>= 1) {
        if (tid < stride) s[tid] += s[tid + stride];
        __syncthreads();
    }
    if (tid == 0)
        out[OFF_LOSS] = s[0] * (1.0f + BETA) / (float)SZ_U;
}

// ---------------------------------------------------------------------------
extern "C" void kernel_launch(void* const* d_in, const int* in_sizes, int n_in,
                              void* d_out, int out_size) {
    const float* u  = (const float*)d_in[0];
    const float* cb = (const float*)d_in[1];
    float* out = (float*)d_out;

    prep_kernel<<<KCODES, 256>>>(cb);
    unorm_kernel<<<dim3(8, B_), 128>>>(u);
    gemm_kernel<<<dim3(NTILE, NTOK / TOKT), 256>>>(u, cb);
    reduce_kernel<<<NTOK / 256, 256>>>(out + OFF_IDX);
    rescue_kernel<<<256, 256>>>(u, cb, out + OFF_IDX);
    epilogue_kernel<<<dim3(C_, B_), 256>>>(u, out);
    loss_kernel<<<1, 256>>>(out);
}

// round 12
// speedup vs baseline: 2.4731x; 1.1032x over previous
#include <cuda_runtime.h>
#include <cuda_bf16.h>
#include <cstdint>

// Problem constants
#define B_      32
#define C_      256
#define HW_     1024
#define NTOK    32768
#define KCODES  1024
#define BETA    0.25f

// Output layout (concatenated float32): u, z_train, vq_loss, indices
#define SZ_U    8388608
#define OFF_U   0
#define OFF_ZT  8388608
#define OFF_LOSS 16777216
#define OFF_IDX  16777217

// GEMM tiling
#define TOKT 256
#define CODT 64
#define NTILE (KCODES / CODT)   // 16
#define SA   264        // A smem stride: %32==8 -> conflict-free frags
#define SB   36         // B smem stride: %32==4 -> conflict-free frags
#define GEMM_SMEM ((2 * 32 * SA + 2 * CODT * SB) * 4)   // 86016 B

// Device scratch
__device__ float g_codebookT[C_ * KCODES];     // [c][code]
__device__ float g_cnorm[KCODES];
__device__ unsigned g_cmax_bits;
__device__ float g_unorm[NTOK];
__device__ int   g_idx[NTOK];
__device__ float g_partial[B_ * C_];
__device__ __align__(16) float4 g_sum[NTOK * NTILE];   // {m1, m2, idx_bits, pad}
__device__ int   g_nambig;
__device__ int   g_ambig[NTOK];
__device__ float g_lim[NTOK];

// ---------------------------------------------------------------------------
__device__ __forceinline__ float to_tf32f(float f) {
    uint32_t r;
    asm("cvt.rna.tf32.f32 %0, %1;" : "=r"(r) : "f"(f));
    return __uint_as_float(r);
}
__device__ __forceinline__ uint32_t tf32b(float f) {
    uint32_t r;
    asm("cvt.rna.tf32.f32 %0, %1;" : "=r"(r) : "f"(f));
    return r;
}

#define CPA16(dst, src) \
    asm volatile("cp.async.cg.shared.global [%0], [%1], 16;" :: "r"(dst), "l"(src))
#define CPA_COMMIT() asm volatile("cp.async.commit_group;" ::: "memory")
#define CPA_WAIT0()  asm volatile("cp.async.wait_group 0;" ::: "memory")

__device__ __forceinline__ void mma_tf32(float* c, const uint32_t* a,
                                         const uint32_t* b) {
    asm volatile(
        "mma.sync.aligned.m16n8k8.row.col.f32.tf32.tf32.f32 "
        "{%0,%1,%2,%3}, {%4,%5,%6,%7}, {%8,%9}, {%0,%1,%2,%3};"
        : "+f"(c[0]), "+f"(c[1]), "+f"(c[2]), "+f"(c[3])
        : "r"(a[0]), "r"(a[1]), "r"(a[2]), "r"(a[3]), "r"(b[0]), "r"(b[1]));
}

__device__ __forceinline__ void upd_min2(float v, int i, float& m1, int& i1,
                                         float& m2) {
    if (v < m1) { m2 = m1; m1 = v; i1 = i; }
    else if (v < m2) { m2 = v; }
}

__device__ __forceinline__ void merge_min2(float& v1, int& i1, float& v2,
                                           float ov1, int oi1, float ov2) {
    if (ov1 < v1 || (ov1 == v1 && oi1 < i1)) {
        v2 = fminf(v1, ov2);
        v1 = ov1; i1 = oi1;
    } else {
        v2 = fminf(v2, ov1);
    }
}

// ---------------------------------------------------------------------------
// K0: codebook transpose + |c|^2 + cmax + zero ambig counter
// ---------------------------------------------------------------------------
__global__ void __launch_bounds__(256) prep_kernel(const float* __restrict__ cb) {
    __shared__ float s[256];
    int k = blockIdx.x;
    int c = threadIdx.x;
    if (k == 0 && c == 0) g_nambig = 0;
    float v = cb[k * C_ + c];
    g_codebookT[c * KCODES + k] = v;
    s[c] = v * v;
    __syncthreads();
    #pragma unroll
    for (int stride = 128; stride > 0; stride >>= 1) {
        if (c < stride) s[c] += s[c + stride];
        __syncthreads();
    }
    if (c == 0) {
        g_cnorm[k] = s[0];
        atomicMax(&g_cmax_bits, __float_as_uint(s[0]));
    }
}

// K0b: per-token ||u||
__global__ void __launch_bounds__(128) unorm_kernel(const float* __restrict__ u) {
    const int b = blockIdx.y;
    const int hw = blockIdx.x * 128 + threadIdx.x;
    const float* up = u + (size_t)b * (C_ * HW_) + hw;
    float acc = 0.f;
    #pragma unroll 8
    for (int c = 0; c < C_; ++c) {
        float v = up[c * HW_];
        acc = fmaf(v, v, acc);
    }
    g_unorm[(b << 10) + hw] = sqrtf(acc) * 1.0002f;
}

// ---------------------------------------------------------------------------
// K1: tf32 GEMM, cp.async double-buffered staging, fused per-tile argmin.
// A staged raw fp32 (cvt at fragment load); B cvt-staged via registers.
// ---------------------------------------------------------------------------
__global__ void __launch_bounds__(256, 2) gemm_kernel(const float* __restrict__ u,
                                                      const float* __restrict__ cb) {
    extern __shared__ float sm[];
    float* Abuf = sm;                       // [2][32*SA] raw fp32
    float* Bbuf = sm + 2 * 32 * SA;         // [2][CODT*SB] tf32

    const int tid = threadIdx.x;
    const int w = tid >> 5, lane = tid & 31;
    const int g = lane >> 2, q = lane & 3;
    const int code0 = blockIdx.x * CODT;
    const int tok0 = blockIdx.y * TOKT;
    const int b = tok0 >> 10, hw0 = tok0 & 1023;
    const float* ub = u + (size_t)b * (C_ * HW_) + hw0;

    float acc[2][8][4];
    #pragma unroll
    for (int m = 0; m < 2; ++m)
        #pragma unroll
        for (int j = 0; j < 8; ++j)
            #pragma unroll
            for (int e = 0; e < 4; ++e) acc[m][j][e] = 0.f;

    // per-thread staging coords (fixed across chunks)
    const int akr0 = tid >> 6, at4 = (tid & 63) << 2;        // A: +p*4 rows
    const int bcr0 = tid >> 3, bk4 = (tid & 7) << 2;         // B: +p*32 rows

    // ---- staging helpers ----
    float4 breg[2];
    #define STAGE_A(kc, buf) do {                                              \
        float* Ab_ = Abuf + (buf) * (32 * SA);                                 \
        const int k0_ = (kc) * 32;                                             \
        _Pragma("unroll")                                                      \
        for (int p = 0; p < 8; ++p) {                                          \
            int kr = akr0 + p * 4;                                             \
            uint32_t dst = (uint32_t)__cvta_generic_to_shared(                 \
                &Ab_[kr * SA + at4]);                                          \
            CPA16(dst, &ub[(size_t)(k0_ + kr) * HW_ + at4]);                   \
        }                                                                      \
    } while (0)
    #define LOAD_B(kc) do {                                                    \
        const int k0_ = (kc) * 32;                                             \
        _Pragma("unroll")                                                      \
        for (int p = 0; p < 2; ++p) {                                          \
            int cr = bcr0 + p * 32;                                            \
            float4 v = *(const float4*)&cb[(size_t)(code0 + cr) * C_ + k0_ + bk4]; \
            v.x = to_tf32f(v.x); v.y = to_tf32f(v.y);                          \
            v.z = to_tf32f(v.z); v.w = to_tf32f(v.w);                          \
            breg[p] = v;                                                       \
        }                                                                      \
    } while (0)
    #define STORE_B(buf) do {                                                  \
        float* Bb_ = Bbuf + (buf) * (CODT * SB);                               \
        _Pragma("unroll")                                                      \
        for (int p = 0; p < 2; ++p) {                                          \
            int cr = bcr0 + p * 32;                                            \
            *(float4*)&Bb_[cr * SB + bk4] = breg[p];                           \
        }                                                                      \
    } while (0)

    // prologue: stage chunk 0 into buffer 0
    STAGE_A(0, 0); CPA_COMMIT();
    LOAD_B(0); STORE_B(0);
    CPA_WAIT0();
    __syncthreads();

    for (int kc = 0; kc < 8; ++kc) {
        const int buf = kc & 1;
        if (kc < 7) {
            STAGE_A(kc + 1, buf ^ 1); CPA_COMMIT();
            LOAD_B(kc + 1); STORE_B(buf ^ 1);
        }

        const float* Ab = Abuf + buf * (32 * SA);
        const uint32_t* Bu = (const uint32_t*)(Bbuf + buf * (CODT * SB));

        #pragma unroll
        for (int ks = 0; ks < 4; ++ks) {
            const int kb = ks * 8;
            uint32_t bf[8][2];
            #pragma unroll
            for (int j = 0; j < 8; ++j) {
                int row = (j * 8 + g) * SB + kb + q;
                bf[j][0] = Bu[row];
                bf[j][1] = Bu[row + 4];
            }
            #pragma unroll
            for (int m = 0; m < 2; ++m) {
                const int arow = w * 32 + m * 16 + g;
                uint32_t af[4];
                af[0] = tf32b(Ab[(kb + q) * SA + arow]);
                af[1] = tf32b(Ab[(kb + q) * SA + arow + 8]);
                af[2] = tf32b(Ab[(kb + q + 4) * SA + arow]);
                af[3] = tf32b(Ab[(kb + q + 4) * SA + arow + 8]);
                #pragma unroll
                for (int j = 0; j < 8; ++j) mma_tf32(acc[m][j], af, bf[j]);
            }
        }
        if (kc < 7) CPA_WAIT0();
        __syncthreads();
    }

    // fused per-tile argmin epilogue
    #pragma unroll
    for (int m = 0; m < 2; ++m) {
        float m1a = 3.4e38f, m2a = 3.4e38f; int i1a = 0;
        float m1b = 3.4e38f, m2b = 3.4e38f; int i1b = 0;
        #pragma unroll
        for (int j = 0; j < 8; ++j) {
            const int col = code0 + j * 8 + q * 2;
            const float cn0 = __ldg(&g_cnorm[col]);
            const float cn1 = __ldg(&g_cnorm[col + 1]);
            upd_min2(fmaf(-2.f, acc[m][j][0], cn0), col,     m1a, i1a, m2a);
            upd_min2(fmaf(-2.f, acc[m][j][1], cn1), col + 1, m1a, i1a, m2a);
            upd_min2(fmaf(-2.f, acc[m][j][2], cn0), col,     m1b, i1b, m2b);
            upd_min2(fmaf(-2.f, acc[m][j][3], cn1), col + 1, m1b, i1b, m2b);
        }
        #pragma unroll
        for (int off = 1; off <= 2; off <<= 1) {
            float ov1 = __shfl_xor_sync(0xffffffffu, m1a, off);
            int   oi1 = __shfl_xor_sync(0xffffffffu, i1a, off);
            float ov2 = __shfl_xor_sync(0xffffffffu, m2a, off);
            merge_min2(m1a, i1a, m2a, ov1, oi1, ov2);
            ov1 = __shfl_xor_sync(0xffffffffu, m1b, off);
            oi1 = __shfl_xor_sync(0xffffffffu, i1b, off);
            ov2 = __shfl_xor_sync(0xffffffffu, m2b, off);
            merge_min2(m1b, i1b, m2b, ov1, oi1, ov2);
        }
        if (q == 0) {
            const int t_lo = tok0 + w * 32 + m * 16 + g;
            g_sum[(size_t)t_lo * NTILE + blockIdx.x] =
                make_float4(m1a, m2a, __int_as_float(i1a), 0.f);
            g_sum[(size_t)(t_lo + 8) * NTILE + blockIdx.x] =
                make_float4(m1b, m2b, __int_as_float(i1b), 0.f);
        }
    }
}

// ---------------------------------------------------------------------------
// K2: reduce. Thread per token; 16 contiguous float4 summary reads.
// ---------------------------------------------------------------------------
__global__ void __launch_bounds__(256) reduce_kernel(float* __restrict__ out_idx) {
    const int tok = blockIdx.x * 256 + threadIdx.x;
    const float4* sp = g_sum + (size_t)tok * NTILE;
    float m1 = 3.4e38f, m2 = 3.4e38f;
    int i1 = 0;
    #pragma unroll
    for (int t = 0; t < NTILE; ++t) {
        float4 s = sp[t];
        merge_min2(m1, i1, m2, s.x, __float_as_int(s.z), s.y);
    }
    g_idx[tok] = i1;
    out_idx[tok] = (float)i1;
    const float cmax = sqrtf(__uint_as_float(g_cmax_bits)) * 1.0002f;
    const float margin = g_unorm[tok] * cmax * (1.02f / 512.f) + 2e-3f;
    if (m2 - m1 <= margin) {
        int slot = atomicAdd(&g_nambig, 1);
        g_ambig[slot] = tok;
        g_lim[slot] = m1 + margin;
    }
}

// ---------------------------------------------------------------------------
// K3: worklist rescue. Warp per entry; float4-coalesced exact dots.
// ---------------------------------------------------------------------------
__global__ void __launch_bounds__(256) rescue_kernel(const float* __restrict__ u,
                                                     const float* __restrict__ cb,
                                                     float* __restrict__ out_idx) {
    __shared__ __align__(16) float us[8][C_];
    const int wid = threadIdx.x >> 5, lane = threadIdx.x & 31;
    const int gw = blockIdx.x * 8 + wid;
    const int nwarps = gridDim.x * 8;
    const int n = g_nambig;

    const int group = lane >> 3;
    const int ks = (lane & 7) << 2;

    for (int i = gw; i < n; i += nwarps) {
        const int tok = g_ambig[i];
        const float lim = g_lim[i];
        const int b = tok >> 10, hw = tok & 1023;
        #pragma unroll
        for (int r = 0; r < 8; ++r) {
            int c = lane + r * 32;
            us[wid][c] = u[((size_t)(b * C_ + c) << 10) + hw];
        }
        __syncwarp();
        float4 uu[8];
        #pragma unroll
        for (int r = 0; r < 8; ++r)
            uu[r] = *(const float4*)&us[wid][ks + r * 32];

        const float4* sp = g_sum + (size_t)tok * NTILE;
        float best = 3.4e38f;
        int bi = KCODES;
        for (int t = 0; t < NTILE; ++t) {
            if (sp[t].x > lim) continue;
            const int cb0 = t * CODT;
            #pragma unroll 4
            for (int p = 0; p < 16; ++p) {
                const int cg = cb0 + p * 4 + group;
                const float* cp = cb + (size_t)cg * C_ + ks;
                float d = 0.f;
                #pragma unroll
                for (int r = 0; r < 8; ++r) {
                    float4 x = *(const float4*)&cp[r * 32];
                    d = fmaf(x.x, uu[r].x, d);
                    d = fmaf(x.y, uu[r].y, d);
                    d = fmaf(x.z, uu[r].z, d);
                    d = fmaf(x.w, uu[r].w, d);
                }
                d += __shfl_xor_sync(0xffffffffu, d, 1);
                d += __shfl_xor_sync(0xffffffffu, d, 2);
                d += __shfl_xor_sync(0xffffffffu, d, 4);
                const float s = fmaf(-2.f, d, __ldg(&g_cnorm[cg]));
                if (s < best || (s == best && cg < bi)) { best = s; bi = cg; }
            }
        }
        #pragma unroll
        for (int off = 16; off > 0; off >>= 1) {
            float ov = __shfl_xor_sync(0xffffffffu, best, off);
            int oi = __shfl_xor_sync(0xffffffffu, bi, off);
            if (ov < best || (ov == best && oi < bi)) { best = ov; bi = oi; }
        }
        if (lane == 0) {
            g_idx[tok] = bi;
            out_idx[tok] = (float)bi;
        }
        __syncwarp();
    }
}

// ---------------------------------------------------------------------------
// K4: outputs. copy u, gather z_q, accumulate (z_q - u)^2 per (b,c)
// ---------------------------------------------------------------------------
__global__ void __launch_bounds__(256) epilogue_kernel(const float* __restrict__ u,
                                                       float* __restrict__ out) {
    __shared__ float col[KCODES];
    __shared__ float sred[256];
    const int c = blockIdx.x;
    const int b = blockIdx.y;
    const int tid = threadIdx.x;

    ((float4*)col)[tid] = ((const float4*)(g_codebookT + c * KCODES))[tid];
    __syncthreads();

    const long base = ((long)(b * C_ + c)) << 10;
    const float* ub = u + base;
    float* ou = out + OFF_U + base;
    float* oz = out + OFF_ZT + base;
    const int* ib = g_idx + (b << 10);

    float acc = 0.f;
    #pragma unroll
    for (int j = 0; j < 4; ++j) {
        int hw = tid + (j << 8);
        int i = ib[hw];
        float z = col[i];
        float uu = ub[hw];
        ou[hw] = uu;
        oz[hw] = z;
        float d = z - uu;
        acc = fmaf(d, d, acc);
    }
    sred[tid] = acc;
    __syncthreads();
    #pragma unroll
    for (int stride = 128; stride > 0; stride >>= 1) {
        if (tid < stride) sred[tid] += sred[tid + stride];
        __syncthreads();
    }
    if (tid == 0) g_partial[b * C_ + c] = sred[0];
}

// ---------------------------------------------------------------------------
// K5: final loss
// ---------------------------------------------------------------------------
__global__ void __launch_bounds__(256) loss_kernel(float* __restrict__ out) {
    __shared__ float s[256];
    const int tid = threadIdx.x;
    float a = 0.f;
    for (int i = tid; i < B_ * C_; i += 256) a += g_partial[i];
    s[tid] = a;
    __syncthreads();
    #pragma unroll
    for (int stride = 128; stride > 0; stride >>= 1) {
        if (tid < stride) s[tid] += s[tid + stride];
        __syncthreads();
    }
    if (tid == 0)
        out[OFF_LOSS] = s[0] * (1.0f + BETA) / (float)SZ_U;
}

// ---------------------------------------------------------------------------
extern "C" void kernel_launch(void* const* d_in, const int* in_sizes, int n_in,
                              void* d_out, int out_size) {
    const float* u  = (const float*)d_in[0];
    const float* cb = (const float*)d_in[1];
    float* out = (float*)d_out;

    static bool attr_done = false;
    if (!attr_done) {
        cudaFuncSetAttribute(gemm_kernel,
                             cudaFuncAttributeMaxDynamicSharedMemorySize,
                             GEMM_SMEM);
        attr_done = true;
    }

    prep_kernel<<<KCODES, 256>>>(cb);
    unorm_kernel<<<dim3(8, B_), 128>>>(u);
    gemm_kernel<<<dim3(NTILE, NTOK / TOKT), 256, GEMM_SMEM>>>(u, cb);
    reduce_kernel<<<NTOK / 256, 256>>>(out + OFF_IDX);
    rescue_kernel<<<256, 256>>>(u, cb, out + OFF_IDX);
    epilogue_kernel<<<dim3(C_, B_), 256>>>(u, out);
    loss_kernel<<<1, 256>>>(out);
}

// round 13
// speedup vs baseline: 2.7335x; 1.1053x over previous
#include <cuda_runtime.h>
#include <cuda_bf16.h>
#include <cuda_fp16.h>
#include <cstdint>

// Problem constants
#define B_      32
#define C_      256
#define HW_     1024
#define NTOK    32768
#define KCODES  1024
#define BETA    0.25f

// Output layout (concatenated float32): u, z_train, vq_loss, indices
#define SZ_U    8388608
#define OFF_U   0
#define OFF_ZT  8388608
#define OFF_LOSS 16777216
#define OFF_IDX  16777217

// GEMM tiling: CTA = 64 codes (MMA-M) x 256 tokens (MMA-N), K=256 in 8x32
#define TOKT 256
#define CODT 64
#define NTILE (KCODES / CODT)   // 16
#define SAU  260        // u smem stride (fp32): 2*SAU%32==8 -> frag conflict-free
#define SAC  40         // cb smem stride (halves)
#define GEMM_SMEM (2 * 32 * SAU * 4 + 2 * CODT * SAC * 2)   // 76800 B

// Device scratch
__device__ float g_codebookT[C_ * KCODES];     // [c][code]
__device__ float g_cnorm[KCODES];
__device__ unsigned g_cmax_bits;
__device__ float g_unorm[NTOK];
__device__ int   g_idx[NTOK];
__device__ float g_partial[B_ * C_];
__device__ __align__(16) float4 g_sum[NTOK * NTILE];   // {m1, m2, idx_bits, pad}
__device__ int   g_nambig;
__device__ int   g_ambig[NTOK];
__device__ float g_lim[NTOK];

// ---------------------------------------------------------------------------
__device__ __forceinline__ uint32_t pack_f16x2(float hi, float lo) {
    uint32_t d;
    asm("cvt.rn.f16x2.f32 %0, %1, %2;" : "=r"(d) : "f"(hi), "f"(lo));
    return d;
}

#define CPA16(dst, src) \
    asm volatile("cp.async.cg.shared.global [%0], [%1], 16;" :: "r"(dst), "l"(src))
#define CPA_COMMIT() asm volatile("cp.async.commit_group;" ::: "memory")
#define CPA_WAIT0()  asm volatile("cp.async.wait_group 0;" ::: "memory")

__device__ __forceinline__ void mma_f16(float* c, const uint32_t* a,
                                        const uint32_t* b) {
    asm volatile(
        "mma.sync.aligned.m16n8k16.row.col.f32.f16.f16.f32 "
        "{%0,%1,%2,%3}, {%4,%5,%6,%7}, {%8,%9}, {%0,%1,%2,%3};"
        : "+f"(c[0]), "+f"(c[1]), "+f"(c[2]), "+f"(c[3])
        : "r"(a[0]), "r"(a[1]), "r"(a[2]), "r"(a[3]), "r"(b[0]), "r"(b[1]));
}

__device__ __forceinline__ void upd_min2(float v, int i, float& m1, int& i1,
                                         float& m2) {
    if (v < m1) { m2 = m1; m1 = v; i1 = i; }
    else if (v < m2) { m2 = v; }
}

__device__ __forceinline__ void merge_min2(float& v1, int& i1, float& v2,
                                           float ov1, int oi1, float ov2) {
    if (ov1 < v1 || (ov1 == v1 && oi1 < i1)) {
        v2 = fminf(v1, ov2);
        v1 = ov1; i1 = oi1;
    } else {
        v2 = fminf(v2, ov1);
    }
}

// ---------------------------------------------------------------------------
// K0: codebook transpose + |c|^2 + cmax + zero ambig counter
// ---------------------------------------------------------------------------
__global__ void __launch_bounds__(256) prep_kernel(const float* __restrict__ cb) {
    __shared__ float s[256];
    int k = blockIdx.x;
    int c = threadIdx.x;
    if (k == 0 && c == 0) g_nambig = 0;
    float v = cb[k * C_ + c];
    g_codebookT[c * KCODES + k] = v;
    s[c] = v * v;
    __syncthreads();
    #pragma unroll
    for (int stride = 128; stride > 0; stride >>= 1) {
        if (c < stride) s[c] += s[c + stride];
        __syncthreads();
    }
    if (c == 0) {
        g_cnorm[k] = s[0];
        atomicMax(&g_cmax_bits, __float_as_uint(s[0]));
    }
}

// K0b: per-token ||u||
__global__ void __launch_bounds__(128) unorm_kernel(const float* __restrict__ u) {
    const int b = blockIdx.y;
    const int hw = blockIdx.x * 128 + threadIdx.x;
    const float* up = u + (size_t)b * (C_ * HW_) + hw;
    float acc = 0.f;
    #pragma unroll 8
    for (int c = 0; c < C_; ++c) {
        float v = up[c * HW_];
        acc = fmaf(v, v, acc);
    }
    g_unorm[(b << 10) + hw] = sqrtf(acc) * 1.0002f;
}

// ---------------------------------------------------------------------------
// K1: fp16 tensor GEMM (codes=M, tokens=N), cp.async double-buffered u,
// f16 codebook tile, fused per-tile argmin over the M (code) dimension.
// grid (16 code-tiles, 128 token-tiles), 256 threads (8 warps).
// Warp tile: 64 codes (4 m-tiles) x 32 tokens (4 n-tiles).
// ---------------------------------------------------------------------------
__global__ void __launch_bounds__(256, 2) gemm_kernel(const float* __restrict__ u,
                                                      const float* __restrict__ cb) {
    extern __shared__ float sm[];
    float* Ubuf = sm;                               // [2][32*SAU] raw fp32
    __half* Abuf = (__half*)(sm + 2 * 32 * SAU);    // [2][CODT*SAC] f16

    const int tid = threadIdx.x;
    const int w = tid >> 5, lane = tid & 31;
    const int g = lane >> 2, q = lane & 3;
    const int code0 = blockIdx.x * CODT;
    const int tok0 = blockIdx.y * TOKT;
    const int b = tok0 >> 10, hw0 = tok0 & 1023;
    const float* ub = u + (size_t)b * (C_ * HW_) + hw0;

    float acc[4][4][4];
    #pragma unroll
    for (int mt = 0; mt < 4; ++mt)
        #pragma unroll
        for (int nt = 0; nt < 4; ++nt)
            #pragma unroll
            for (int e = 0; e < 4; ++e) acc[mt][nt][e] = 0.f;

    // staging coords
    const int ukr0 = tid >> 6, ut4 = (tid & 63) << 2;  // u: rows +p*4
    const int ccr0 = tid >> 3, ck4 = (tid & 7) << 2;   // cb: rows +p*32

    float4 creg[2];
    #define STAGE_U(kc, buf) do {                                              \
        float* Ub_ = Ubuf + (buf) * (32 * SAU);                                \
        const int k0_ = (kc) * 32;                                             \
        _Pragma("unroll")                                                      \
        for (int p = 0; p < 8; ++p) {                                          \
            int kr = ukr0 + p * 4;                                             \
            uint32_t dst = (uint32_t)__cvta_generic_to_shared(                 \
                &Ub_[kr * SAU + ut4]);                                         \
            CPA16(dst, &ub[(size_t)(k0_ + kr) * HW_ + ut4]);                   \
        }                                                                      \
    } while (0)
    #define LOAD_CB(kc) do {                                                   \
        const int k0_ = (kc) * 32;                                             \
        _Pragma("unroll")                                                      \
        for (int p = 0; p < 2; ++p) {                                          \
            int cr = ccr0 + p * 32;                                            \
            creg[p] = *(const float4*)&cb[(size_t)(code0 + cr) * C_ + k0_ + ck4]; \
        }                                                                      \
    } while (0)
    #define STORE_CB(buf) do {                                                 \
        __half* Ab_ = Abuf + (buf) * (CODT * SAC);                             \
        _Pragma("unroll")                                                      \
        for (int p = 0; p < 2; ++p) {                                          \
            int cr = ccr0 + p * 32;                                            \
            uint2 wv;                                                          \
            wv.x = pack_f16x2(creg[p].y, creg[p].x);                           \
            wv.y = pack_f16x2(creg[p].w, creg[p].z);                           \
            *(uint2*)(Ab_ + cr * SAC + ck4) = wv;                              \
        }                                                                      \
    } while (0)

    // prologue
    STAGE_U(0, 0); CPA_COMMIT();
    LOAD_CB(0); STORE_CB(0);
    CPA_WAIT0();
    __syncthreads();

    for (int kc = 0; kc < 8; ++kc) {
        const int buf = kc & 1;
        if (kc < 7) {
            STAGE_U(kc + 1, buf ^ 1); CPA_COMMIT();
            LOAD_CB(kc + 1); STORE_CB(buf ^ 1);
        }

        const float* Ub = Ubuf + buf * (32 * SAU);
        const __half* Ab = Abuf + buf * (CODT * SAC);

        #pragma unroll
        for (int ks = 0; ks < 2; ++ks) {
            const int kb = ks * 16;
            // B fragments (tokens): 4 n-tiles x 2 regs; fp32 LDS + cvt-pack
            uint32_t bf[4][2];
            #pragma unroll
            for (int nt = 0; nt < 4; ++nt) {
                const int col = w * 32 + nt * 8 + g;
                float x0 = Ub[(kb + 2 * q) * SAU + col];
                float x1 = Ub[(kb + 2 * q + 1) * SAU + col];
                bf[nt][0] = pack_f16x2(x1, x0);
                float x2 = Ub[(kb + 2 * q + 8) * SAU + col];
                float x3 = Ub[(kb + 2 * q + 9) * SAU + col];
                bf[nt][1] = pack_f16x2(x3, x2);
            }
            // A fragments (codes): 4 m-tiles x 4 half2 regs
            uint32_t af[4][4];
            #pragma unroll
            for (int mt = 0; mt < 4; ++mt) {
                const int r0 = (mt * 16 + g) * SAC + kb + 2 * q;
                const int r1 = (mt * 16 + g + 8) * SAC + kb + 2 * q;
                af[mt][0] = *(const uint32_t*)(Ab + r0);
                af[mt][1] = *(const uint32_t*)(Ab + r1);
                af[mt][2] = *(const uint32_t*)(Ab + r0 + 8);
                af[mt][3] = *(const uint32_t*)(Ab + r1 + 8);
            }
            #pragma unroll
            for (int mt = 0; mt < 4; ++mt)
                #pragma unroll
                for (int nt = 0; nt < 4; ++nt)
                    mma_f16(acc[mt][nt], af[mt], bf[nt]);
        }
        if (kc < 7) CPA_WAIT0();
        __syncthreads();
    }

    // fused argmin over codes (M): per thread 8 codes/token, merge over g
    #pragma unroll
    for (int nt = 0; nt < 4; ++nt) {
        #pragma unroll
        for (int e = 0; e < 2; ++e) {
            float m1 = 3.4e38f, m2 = 3.4e38f;
            int i1 = 0;
            #pragma unroll
            for (int mt = 0; mt < 4; ++mt) {
                const int clo = code0 + mt * 16 + g;
                upd_min2(fmaf(-2.f, acc[mt][nt][e], __ldg(&g_cnorm[clo])),
                         clo, m1, i1, m2);
                upd_min2(fmaf(-2.f, acc[mt][nt][2 + e], __ldg(&g_cnorm[clo + 8])),
                         clo + 8, m1, i1, m2);
            }
            #pragma unroll
            for (int off = 4; off <= 16; off <<= 1) {
                float ov1 = __shfl_xor_sync(0xffffffffu, m1, off);
                int   oi1 = __shfl_xor_sync(0xffffffffu, i1, off);
                float ov2 = __shfl_xor_sync(0xffffffffu, m2, off);
                merge_min2(m1, i1, m2, ov1, oi1, ov2);
            }
            if (g == 0) {
                const int tok = tok0 + w * 32 + nt * 8 + 2 * q + e;
                g_sum[(size_t)tok * NTILE + blockIdx.x] =
                    make_float4(m1, m2, __int_as_float(i1), 0.f);
            }
        }
    }
}

// ---------------------------------------------------------------------------
// K2: reduce. Thread per token; 16 contiguous float4 summary reads.
// ---------------------------------------------------------------------------
__global__ void __launch_bounds__(256) reduce_kernel(float* __restrict__ out_idx) {
    const int tok = blockIdx.x * 256 + threadIdx.x;
    const float4* sp = g_sum + (size_t)tok * NTILE;
    float m1 = 3.4e38f, m2 = 3.4e38f;
    int i1 = 0;
    #pragma unroll
    for (int t = 0; t < NTILE; ++t) {
        float4 s = sp[t];
        merge_min2(m1, i1, m2, s.x, __float_as_int(s.z), s.y);
    }
    g_idx[tok] = i1;
    out_idx[tok] = (float)i1;
    const float cmax = sqrtf(__uint_as_float(g_cmax_bits)) * 1.0002f;
    const float margin = g_unorm[tok] * cmax * (1.02f / 512.f) + 2e-3f;
    if (m2 - m1 <= margin) {
        int slot = atomicAdd(&g_nambig, 1);
        g_ambig[slot] = tok;
        g_lim[slot] = m1 + margin;
    }
}

// ---------------------------------------------------------------------------
// K3: worklist rescue. Warp per entry; float4-coalesced exact fp32 dots.
// ---------------------------------------------------------------------------
__global__ void __launch_bounds__(256) rescue_kernel(const float* __restrict__ u,
                                                     const float* __restrict__ cb,
                                                     float* __restrict__ out_idx) {
    __shared__ __align__(16) float us[8][C_];
    const int wid = threadIdx.x >> 5, lane = threadIdx.x & 31;
    const int gw = blockIdx.x * 8 + wid;
    const int nwarps = gridDim.x * 8;
    const int n = g_nambig;

    const int group = lane >> 3;
    const int ks = (lane & 7) << 2;

    for (int i = gw; i < n; i += nwarps) {
        const int tok = g_ambig[i];
        const float lim = g_lim[i];
        const int b = tok >> 10, hw = tok & 1023;
        #pragma unroll
        for (int r = 0; r < 8; ++r) {
            int c = lane + r * 32;
            us[wid][c] = u[((size_t)(b * C_ + c) << 10) + hw];
        }
        __syncwarp();
        float4 uu[8];
        #pragma unroll
        for (int r = 0; r < 8; ++r)
            uu[r] = *(const float4*)&us[wid][ks + r * 32];

        const float4* sp = g_sum + (size_t)tok * NTILE;
        float best = 3.4e38f;
        int bi = KCODES;
        for (int t = 0; t < NTILE; ++t) {
            if (sp[t].x > lim) continue;
            const int cb0 = t * CODT;
            #pragma unroll 4
            for (int p = 0; p < 16; ++p) {
                const int cg = cb0 + p * 4 + group;
                const float* cp = cb + (size_t)cg * C_ + ks;
                float d = 0.f;
                #pragma unroll
                for (int r = 0; r < 8; ++r) {
                    float4 x = *(const float4*)&cp[r * 32];
                    d = fmaf(x.x, uu[r].x, d);
                    d = fmaf(x.y, uu[r].y, d);
                    d = fmaf(x.z, uu[r].z, d);
                    d = fmaf(x.w, uu[r].w, d);
                }
                d += __shfl_xor_sync(0xffffffffu, d, 1);
                d += __shfl_xor_sync(0xffffffffu, d, 2);
                d += __shfl_xor_sync(0xffffffffu, d, 4);
                const float s = fmaf(-2.f, d, __ldg(&g_cnorm[cg]));
                if (s < best || (s == best && cg < bi)) { best = s; bi = cg; }
            }
        }
        #pragma unroll
        for (int off = 16; off > 0; off >>= 1) {
            float ov = __shfl_xor_sync(0xffffffffu, best, off);
            int oi = __shfl_xor_sync(0xffffffffu, bi, off);
            if (ov < best || (ov == best && oi < bi)) { best = ov; bi = oi; }
        }
        if (lane == 0) {
            g_idx[tok] = bi;
            out_idx[tok] = (float)bi;
        }
        __syncwarp();
    }
}

// ---------------------------------------------------------------------------
// K4: outputs. copy u, gather z_q, accumulate (z_q - u)^2 per (b,c)
// ---------------------------------------------------------------------------
__global__ void __launch_bounds__(256) epilogue_kernel(const float* __restrict__ u,
                                                       float* __restrict__ out) {
    __shared__ float col[KCODES];
    __shared__ float sred[256];
    const int c = blockIdx.x;
    const int b = blockIdx.y;
    const int tid = threadIdx.x;

    ((float4*)col)[tid] = ((const float4*)(g_codebookT + c * KCODES))[tid];
    __syncthreads();

    const long base = ((long)(b * C_ + c)) << 10;
    const float* ub = u + base;
    float* ou = out + OFF_U + base;
    float* oz = out + OFF_ZT + base;
    const int* ib = g_idx + (b << 10);

    float acc = 0.f;
    #pragma unroll
    for (int j = 0; j < 4; ++j) {
        int hw = tid + (j << 8);
        int i = ib[hw];
        float z = col[i];
        float uu = ub[hw];
        ou[hw] = uu;
        oz[hw] = z;
        float d = z - uu;
        acc = fmaf(d, d, acc);
    }
    sred[tid] = acc;
    __syncthreads();
    #pragma unroll
    for (int stride = 128; stride > 0; stride >>= 1) {
        if (tid < stride) sred[tid] += sred[tid + stride];
        __syncthreads();
    }
    if (tid == 0) g_partial[b * C_ + c] = sred[0];
}

// ---------------------------------------------------------------------------
// K5: final loss
// ---------------------------------------------------------------------------
__global__ void __launch_bounds__(256) loss_kernel(float* __restrict__ out) {
    __shared__ float s[256];
    const int tid = threadIdx.x;
    float a = 0.f;
    for (int i = tid; i < B_ * C_; i += 256) a += g_partial[i];
    s[tid] = a;
    __syncthreads();
    #pragma unroll
    for (int stride = 128; stride > 0; stride >>= 1) {
        if (tid < stride) s[tid] += s[tid + stride];
        __syncthreads();
    }
    if (tid == 0)
        out[OFF_LOSS] = s[0] * (1.0f + BETA) / (float)SZ_U;
}

// ---------------------------------------------------------------------------
extern "C" void kernel_launch(void* const* d_in, const int* in_sizes, int n_in,
                              void* d_out, int out_size) {
    const float* u  = (const float*)d_in[0];
    const float* cb = (const float*)d_in[1];
    float* out = (float*)d_out;

    static bool attr_done = false;
    if (!attr_done) {
        cudaFuncSetAttribute(gemm_kernel,
                             cudaFuncAttributeMaxDynamicSharedMemorySize,
                             GEMM_SMEM);
        attr_done = true;
    }

    prep_kernel<<<KCODES, 256>>>(cb);
    unorm_kernel<<<dim3(8, B_), 128>>>(u);
    gemm_kernel<<<dim3(NTILE, NTOK / TOKT), 256, GEMM_SMEM>>>(u, cb);
    reduce_kernel<<<NTOK / 256, 256>>>(out + OFF_IDX);
    rescue_kernel<<<512, 256>>>(u, cb, out + OFF_IDX);
    epilogue_kernel<<<dim3(C_, B_), 256>>>(u, out);
    loss_kernel<<<1, 256>>>(out);
}

// round 14
// speedup vs baseline: 2.8733x; 1.0512x over previous
#include <cuda_runtime.h>
#include <cuda_bf16.h>
#include <cuda_fp16.h>
#include <cstdint>

// Problem constants
#define B_      32
#define C_      256
#define HW_     1024
#define NTOK    32768
#define KCODES  1024
#define BETA    0.25f

// Output layout (concatenated float32): u, z_train, vq_loss, indices
#define SZ_U    8388608
#define OFF_U   0
#define OFF_ZT  8388608
#define OFF_LOSS 16777216
#define OFF_IDX  16777217

// GEMM tiling: CTA = 64 codes (MMA-M) x 256 tokens (MMA-N), K=256 in 8x32
#define TOKT 256
#define CODT 64
#define NTILE (KCODES / CODT)   // 16
#define SAU_H 264       // u16 smem stride (halves): 33x16B rows, 33%8==1 -> ldsm ok
#define SAC_H 40        // cb16 smem stride (halves): 5x16B rows, 5%8!=0 -> ldsm ok
#define GEMM_SMEM (2 * 32 * SAU_H * 2 + 2 * CODT * SAC_H * 2)   // 44032 B

// Device scratch
__device__ float g_codebookT[C_ * KCODES];     // [c][code]
__device__ float g_cnorm[KCODES];
__device__ unsigned g_cmax_bits;
__device__ float g_unorm[NTOK];
__device__ int   g_idx[NTOK];
__device__ float g_partial[B_ * C_];
__device__ __align__(16) __half g_u16[NTOK * C_];    // [b][c][hw] f16, 16 MB
__device__ __align__(16) __half g_cb16[KCODES * C_]; // [code][k] f16
__device__ __align__(16) float4 g_sum[NTOK * NTILE]; // {m1, m2, idx_bits, pad}
__device__ int   g_nambig;
__device__ int   g_ambig[NTOK];
__device__ float g_lim[NTOK];

// ---------------------------------------------------------------------------
__device__ __forceinline__ uint32_t pack_f16x2(float hi, float lo) {
    uint32_t d;
    asm("cvt.rn.f16x2.f32 %0, %1, %2;" : "=r"(d) : "f"(hi), "f"(lo));
    return d;
}

#define CPA16(dst, src) \
    asm volatile("cp.async.cg.shared.global [%0], [%1], 16;" :: "r"(dst), "l"(src))
#define CPA_COMMIT() asm volatile("cp.async.commit_group;" ::: "memory")
#define CPA_WAIT0()  asm volatile("cp.async.wait_group 0;" ::: "memory")

__device__ __forceinline__ void ldsm_x4(uint32_t* r, uint32_t a) {
    asm volatile("ldmatrix.sync.aligned.m8n8.x4.shared.b16 {%0,%1,%2,%3}, [%4];"
        : "=r"(r[0]), "=r"(r[1]), "=r"(r[2]), "=r"(r[3]) : "r"(a));
}
__device__ __forceinline__ void ldsm_x2t(uint32_t* r, uint32_t a) {
    asm volatile("ldmatrix.sync.aligned.m8n8.x2.trans.shared.b16 {%0,%1}, [%2];"
        : "=r"(r[0]), "=r"(r[1]) : "r"(a));
}

__device__ __forceinline__ void mma_f16(float* c, const uint32_t* a,
                                        const uint32_t* b) {
    asm volatile(
        "mma.sync.aligned.m16n8k16.row.col.f32.f16.f16.f32 "
        "{%0,%1,%2,%3}, {%4,%5,%6,%7}, {%8,%9}, {%0,%1,%2,%3};"
        : "+f"(c[0]), "+f"(c[1]), "+f"(c[2]), "+f"(c[3])
        : "r"(a[0]), "r"(a[1]), "r"(a[2]), "r"(a[3]), "r"(b[0]), "r"(b[1]));
}

__device__ __forceinline__ void upd_min2(float v, int i, float& m1, int& i1,
                                         float& m2) {
    if (v < m1) { m2 = m1; m1 = v; i1 = i; }
    else if (v < m2) { m2 = v; }
}

__device__ __forceinline__ void merge_min2(float& v1, int& i1, float& v2,
                                           float ov1, int oi1, float ov2) {
    if (ov1 < v1 || (ov1 == v1 && oi1 < i1)) {
        v2 = fminf(v1, ov2);
        v1 = ov1; i1 = oi1;
    } else {
        v2 = fminf(v2, ov1);
    }
}

// ---------------------------------------------------------------------------
// K0: codebook transpose + |c|^2 + cmax + f16 copy + zero ambig counter
// ---------------------------------------------------------------------------
__global__ void __launch_bounds__(256) prep_kernel(const float* __restrict__ cb) {
    __shared__ float s[256];
    int k = blockIdx.x;
    int c = threadIdx.x;
    if (k == 0 && c == 0) g_nambig = 0;
    float v = cb[k * C_ + c];
    g_codebookT[c * KCODES + k] = v;
    g_cb16[k * C_ + c] = __float2half_rn(v);
    s[c] = v * v;
    __syncthreads();
    #pragma unroll
    for (int stride = 128; stride > 0; stride >>= 1) {
        if (c < stride) s[c] += s[c + stride];
        __syncthreads();
    }
    if (c == 0) {
        g_cnorm[k] = s[0];
        atomicMax(&g_cmax_bits, __float_as_uint(s[0]));
    }
}

// K0b: per-token ||u|| (fp32, exact)
__global__ void __launch_bounds__(128) unorm_kernel(const float* __restrict__ u) {
    const int b = blockIdx.y;
    const int hw = blockIdx.x * 128 + threadIdx.x;
    const float* up = u + (size_t)b * (C_ * HW_) + hw;
    float acc = 0.f;
    #pragma unroll 8
    for (int c = 0; c < C_; ++c) {
        float v = up[c * HW_];
        acc = fmaf(v, v, acc);
    }
    g_unorm[(b << 10) + hw] = sqrtf(acc) * 1.0002f;
}

// K0c: u -> f16. 1024 blocks x 256 thr x 8 float4 = 8,388,608 floats exactly.
__global__ void __launch_bounds__(256) prep_u16_kernel(const float* __restrict__ u) {
    const float4* u4 = (const float4*)u;
    uint2* h4 = (uint2*)g_u16;
    const size_t base = (size_t)blockIdx.x * 2048 + (size_t)threadIdx.x * 8;
    #pragma unroll
    for (int p = 0; p < 8; ++p) {
        float4 v = u4[base + p];
        uint2 wv;
        wv.x = pack_f16x2(v.y, v.x);
        wv.y = pack_f16x2(v.w, v.z);
        h4[base + p] = wv;
    }
}

// ---------------------------------------------------------------------------
// K1: fp16 GEMM, all-f16 smem, cp.async double buffer, ldmatrix operands,
// fused per-tile argmin over codes. grid (16, 128), 256 threads (8 warps).
// ---------------------------------------------------------------------------
__global__ void __launch_bounds__(256, 2) gemm_kernel() {
    extern __shared__ __half smh[];
    __half* Ubuf = smh;                         // [2][32*SAU_H]
    __half* Abuf = smh + 2 * 32 * SAU_H;        // [2][CODT*SAC_H]

    const int tid = threadIdx.x;
    const int w = tid >> 5, lane = tid & 31;
    const int g = lane >> 2, q = lane & 3;
    const int code0 = blockIdx.x * CODT;
    const int tok0 = blockIdx.y * TOKT;
    const int b = tok0 >> 10, hw0 = tok0 & 1023;
    const __half* ub16 = g_u16 + (size_t)b * (C_ * HW_) + hw0;
    const __half* cb16 = g_cb16 + (size_t)code0 * C_;

    float acc[4][4][4];
    #pragma unroll
    for (int mt = 0; mt < 4; ++mt)
        #pragma unroll
        for (int nt = 0; nt < 4; ++nt)
            #pragma unroll
            for (int e = 0; e < 4; ++e) acc[mt][nt][e] = 0.f;

    // ldmatrix per-lane address offsets
    const int a_row = lane & 15, a_col = (lane >> 4) << 3;   // A x4
    const int b_k = lane & 15;                               // B x2.trans

    #define STAGE_U16(kc, buf) do {                                            \
        __half* Ub_ = Ubuf + (buf) * (32 * SAU_H);                              \
        const int k0_ = (kc) * 32;                                              \
        _Pragma("unroll")                                                       \
        for (int p = 0; p < 4; ++p) {                                           \
            int id = tid + p * 256;                                             \
            int kr = id >> 5, cq = id & 31;                                     \
            uint32_t dst = (uint32_t)__cvta_generic_to_shared(                  \
                Ub_ + kr * SAU_H + cq * 8);                                     \
            CPA16(dst, ub16 + (size_t)(k0_ + kr) * HW_ + cq * 8);               \
        }                                                                       \
    } while (0)
    #define STAGE_CB16(kc, buf) do {                                            \
        __half* Ab_ = Abuf + (buf) * (CODT * SAC_H);                             \
        const int k0_ = (kc) * 32;                                               \
        int row = tid >> 2, cq = tid & 3;                                        \
        uint32_t dst = (uint32_t)__cvta_generic_to_shared(                       \
            Ab_ + row * SAC_H + cq * 8);                                         \
        CPA16(dst, cb16 + (size_t)row * C_ + k0_ + cq * 8);                      \
    } while (0)

    // prologue
    STAGE_U16(0, 0);
    STAGE_CB16(0, 0);
    CPA_COMMIT();
    CPA_WAIT0();
    __syncthreads();

    for (int kc = 0; kc < 8; ++kc) {
        const int buf = kc & 1;
        if (kc < 7) {
            STAGE_U16(kc + 1, buf ^ 1);
            STAGE_CB16(kc + 1, buf ^ 1);
            CPA_COMMIT();
        }

        const __half* Ub = Ubuf + buf * (32 * SAU_H);
        const __half* Ab = Abuf + buf * (CODT * SAC_H);
        const int n0 = w * 32;

        #pragma unroll
        for (int ks = 0; ks < 2; ++ks) {
            const int kb = ks * 16;
            uint32_t bf[4][2];
            #pragma unroll
            for (int nt = 0; nt < 4; ++nt) {
                uint32_t a = (uint32_t)__cvta_generic_to_shared(
                    Ub + (kb + b_k) * SAU_H + n0 + nt * 8);
                ldsm_x2t(bf[nt], a);
            }
            uint32_t af[4][4];
            #pragma unroll
            for (int mt = 0; mt < 4; ++mt) {
                uint32_t a = (uint32_t)__cvta_generic_to_shared(
                    Ab + (mt * 16 + a_row) * SAC_H + kb + a_col);
                ldsm_x4(af[mt], a);
            }
            #pragma unroll
            for (int mt = 0; mt < 4; ++mt)
                #pragma unroll
                for (int nt = 0; nt < 4; ++nt)
                    mma_f16(acc[mt][nt], af[mt], bf[nt]);
        }
        if (kc < 7) CPA_WAIT0();
        __syncthreads();
    }

    // fused argmin over codes (M): per thread 8 codes/token, merge over g
    #pragma unroll
    for (int nt = 0; nt < 4; ++nt) {
        #pragma unroll
        for (int e = 0; e < 2; ++e) {
            float m1 = 3.4e38f, m2 = 3.4e38f;
            int i1 = 0;
            #pragma unroll
            for (int mt = 0; mt < 4; ++mt) {
                const int clo = code0 + mt * 16 + g;
                upd_min2(fmaf(-2.f, acc[mt][nt][e], __ldg(&g_cnorm[clo])),
                         clo, m1, i1, m2);
                upd_min2(fmaf(-2.f, acc[mt][nt][2 + e], __ldg(&g_cnorm[clo + 8])),
                         clo + 8, m1, i1, m2);
            }
            #pragma unroll
            for (int off = 4; off <= 16; off <<= 1) {
                float ov1 = __shfl_xor_sync(0xffffffffu, m1, off);
                int   oi1 = __shfl_xor_sync(0xffffffffu, i1, off);
                float ov2 = __shfl_xor_sync(0xffffffffu, m2, off);
                merge_min2(m1, i1, m2, ov1, oi1, ov2);
            }
            if (g == 0) {
                const int tok = tok0 + w * 32 + nt * 8 + 2 * q + e;
                g_sum[(size_t)tok * NTILE + blockIdx.x] =
                    make_float4(m1, m2, __int_as_float(i1), 0.f);
            }
        }
    }
}

// ---------------------------------------------------------------------------
// K2: reduce. Thread per token; 16 contiguous float4 summary reads.
// ---------------------------------------------------------------------------
__global__ void __launch_bounds__(256) reduce_kernel(float* __restrict__ out_idx) {
    const int tok = blockIdx.x * 256 + threadIdx.x;
    const float4* sp = g_sum + (size_t)tok * NTILE;
    float m1 = 3.4e38f, m2 = 3.4e38f;
    int i1 = 0;
    #pragma unroll
    for (int t = 0; t < NTILE; ++t) {
        float4 s = sp[t];
        merge_min2(m1, i1, m2, s.x, __float_as_int(s.z), s.y);
    }
    g_idx[tok] = i1;
    out_idx[tok] = (float)i1;
    const float cmax = sqrtf(__uint_as_float(g_cmax_bits)) * 1.0002f;
    const float margin = g_unorm[tok] * cmax * (1.02f / 512.f) + 2e-3f;
    if (m2 - m1 <= margin) {
        int slot = atomicAdd(&g_nambig, 1);
        g_ambig[slot] = tok;
        g_lim[slot] = m1 + margin;
    }
}

// ---------------------------------------------------------------------------
// K3: worklist rescue. Warp per entry; float4-coalesced exact fp32 dots.
// ---------------------------------------------------------------------------
__global__ void __launch_bounds__(256) rescue_kernel(const float* __restrict__ u,
                                                     const float* __restrict__ cb,
                                                     float* __restrict__ out_idx) {
    __shared__ __align__(16) float us[8][C_];
    const int wid = threadIdx.x >> 5, lane = threadIdx.x & 31;
    const int gw = blockIdx.x * 8 + wid;
    const int nwarps = gridDim.x * 8;
    const int n = g_nambig;

    const int group = lane >> 3;
    const int ks = (lane & 7) << 2;

    for (int i = gw; i < n; i += nwarps) {
        const int tok = g_ambig[i];
        const float lim = g_lim[i];
        const int b = tok >> 10, hw = tok & 1023;
        #pragma unroll
        for (int r = 0; r < 8; ++r) {
            int c = lane + r * 32;
            us[wid][c] = u[((size_t)(b * C_ + c) << 10) + hw];
        }
        __syncwarp();
        float4 uu[8];
        #pragma unroll
        for (int r = 0; r < 8; ++r)
            uu[r] = *(const float4*)&us[wid][ks + r * 32];

        const float4* sp = g_sum + (size_t)tok * NTILE;
        float best = 3.4e38f;
        int bi = KCODES;
        for (int t = 0; t < NTILE; ++t) {
            if (sp[t].x > lim) continue;
            const int cb0 = t * CODT;
            #pragma unroll 4
            for (int p = 0; p < 16; ++p) {
                const int cg = cb0 + p * 4 + group;
                const float* cp = cb + (size_t)cg * C_ + ks;
                float d = 0.f;
                #pragma unroll
                for (int r = 0; r < 8; ++r) {
                    float4 x = *(const float4*)&cp[r * 32];
                    d = fmaf(x.x, uu[r].x, d);
                    d = fmaf(x.y, uu[r].y, d);
                    d = fmaf(x.z, uu[r].z, d);
                    d = fmaf(x.w, uu[r].w, d);
                }
                d += __shfl_xor_sync(0xffffffffu, d, 1);
                d += __shfl_xor_sync(0xffffffffu, d, 2);
                d += __shfl_xor_sync(0xffffffffu, d, 4);
                const float s = fmaf(-2.f, d, __ldg(&g_cnorm[cg]));
                if (s < best || (s == best && cg < bi)) { best = s; bi = cg; }
            }
        }
        #pragma unroll
        for (int off = 16; off > 0; off >>= 1) {
            float ov = __shfl_xor_sync(0xffffffffu, best, off);
            int oi = __shfl_xor_sync(0xffffffffu, bi, off);
            if (ov < best || (ov == best && oi < bi)) { best = ov; bi = oi; }
        }
        if (lane == 0) {
            g_idx[tok] = bi;
            out_idx[tok] = (float)bi;
        }
        __syncwarp();
    }
}

// ---------------------------------------------------------------------------
// K4: outputs. copy u, gather z_q, accumulate (z_q - u)^2 per (b,c)
// ---------------------------------------------------------------------------
__global__ void __launch_bounds__(256) epilogue_kernel(const float* __restrict__ u,
                                                       float* __restrict__ out) {
    __shared__ float col[KCODES];
    __shared__ float sred[256];
    const int c = blockIdx.x;
    const int b = blockIdx.y;
    const int tid = threadIdx.x;

    ((float4*)col)[tid] = ((const float4*)(g_codebookT + c * KCODES))[tid];
    __syncthreads();

    const long base = ((long)(b * C_ + c)) << 10;
    const float* ub = u + base;
    float* ou = out + OFF_U + base;
    float* oz = out + OFF_ZT + base;
    const int* ib = g_idx + (b << 10);

    float acc = 0.f;
    #pragma unroll
    for (int j = 0; j < 4; ++j) {
        int hw = tid + (j << 8);
        int i = ib[hw];
        float z = col[i];
        float uu = ub[hw];
        ou[hw] = uu;
        oz[hw] = z;
        float d = z - uu;
        acc = fmaf(d, d, acc);
    }
    sred[tid] = acc;
    __syncthreads();
    #pragma unroll
    for (int stride = 128; stride > 0; stride >>= 1) {
        if (tid < stride) sred[tid] += sred[tid + stride];
        __syncthreads();
    }
    if (tid == 0) g_partial[b * C_ + c] = sred[0];
}

// ---------------------------------------------------------------------------
// K5: final loss
// ---------------------------------------------------------------------------
__global__ void __launch_bounds__(256) loss_kernel(float* __restrict__ out) {
    __shared__ float s[256];
    const int tid = threadIdx.x;
    float a = 0.f;
    for (int i = tid; i < B_ * C_; i += 256) a += g_partial[i];
    s[tid] = a;
    __syncthreads();
    #pragma unroll
    for (int stride = 128; stride > 0; stride >>= 1) {
        if (tid < stride) s[tid] += s[tid + stride];
        __syncthreads();
    }
    if (tid == 0)
        out[OFF_LOSS] = s[0] * (1.0f + BETA) / (float)SZ_U;
}

// ---------------------------------------------------------------------------
extern "C" void kernel_launch(void* const* d_in, const int* in_sizes, int n_in,
                              void* d_out, int out_size) {
    const float* u  = (const float*)d_in[0];
    const float* cb = (const float*)d_in[1];
    float* out = (float*)d_out;

    static bool attr_done = false;
    if (!attr_done) {
        cudaFuncSetAttribute(gemm_kernel,
                             cudaFuncAttributeMaxDynamicSharedMemorySize,
                             GEMM_SMEM);
        attr_done = true;
    }

    prep_kernel<<<KCODES, 256>>>(cb);
    prep_u16_kernel<<<1024, 256>>>(u);
    unorm_kernel<<<dim3(8, B_), 128>>>(u);
    gemm_kernel<<<dim3(NTILE, NTOK / TOKT), 256, GEMM_SMEM>>>();
    reduce_kernel<<<NTOK / 256, 256>>>(out + OFF_IDX);
    rescue_kernel<<<512, 256>>>(u, cb, out + OFF_IDX);
    epilogue_kernel<<<dim3(C_, B_), 256>>>(u, out);
    loss_kernel<<<1, 256>>>(out);
}